// round 2
// baseline (speedup 1.0000x reference)
#include <cuda_runtime.h>
#include <math.h>

#define N_NODES 100000
#define N_EDGES 1600000
#define IN_CH 128
#define HID 128
#define OUT_CH 40

// -------- scratch (static __device__ globals; no runtime alloc) ----------
__device__ int   g_is64;
__device__ int   g_degi[N_NODES];
__device__ int   g_cursor[N_NODES];
__device__ int   g_rowstart[N_NODES + 1];
__device__ int   g_csrc[N_EDGES];
__device__ float g_aggr1[(size_t)N_NODES * IN_CH];   // mean-aggregated x
__device__ float g_h[(size_t)N_NODES * HID];         // layer-1 output (relu)
__device__ float g_pq[(size_t)N_NODES * 80];         // [p(40) | q(40)] per node

// edge accessor: works for int32 or int64 edge_index
__device__ __forceinline__ int edge_at(const void* ei, long long idx) {
    if (g_is64) return (int)((const long long*)ei)[idx];
    return ((const int*)ei)[idx];
}

// -------------------- dtype detect + zero --------------------
// int64 data with values < N_NODES has zero high 32-bit words; int32 edge data
// (random in [0,100000)) cannot have 256 consecutive zeros at odd positions.
__global__ void k_detect(const int* __restrict__ ei32) {
    __shared__ int nz;
    if (threadIdx.x == 0) nz = 0;
    __syncthreads();
    if (ei32[2 * threadIdx.x + 1] != 0) atomicAdd(&nz, 1);
    __syncthreads();
    if (threadIdx.x == 0) g_is64 = (nz == 0) ? 1 : 0;
}

__global__ void k_zero2() {
    int i = blockIdx.x * blockDim.x + threadIdx.x;
    if (i < N_NODES) { g_degi[i] = 0; g_cursor[i] = 0; }
}

// -------------------- CSR build --------------------

__global__ void k_count(const void* __restrict__ ei) {
    for (int e = blockIdx.x * blockDim.x + threadIdx.x; e < N_EDGES;
         e += gridDim.x * blockDim.x) {
        int d = edge_at(ei, (long long)N_EDGES + e);
        atomicAdd(&g_degi[d], 1);
    }
}

// single-block exclusive scan over 100k degrees
__global__ void k_scan() {
    __shared__ int sh[1024];
    const int CH = (N_NODES + 1023) / 1024;  // 98
    int t = threadIdx.x;
    int start = t * CH;
    int end = min(start + CH, N_NODES);
    int local = 0;
    for (int i = start; i < end; i++) local += g_degi[i];
    sh[t] = local;
    __syncthreads();
    for (int off = 1; off < 1024; off <<= 1) {
        int v = (t >= off) ? sh[t - off] : 0;
        __syncthreads();
        sh[t] += v;
        __syncthreads();
    }
    int run = sh[t] - local;  // exclusive prefix
    for (int i = start; i < end; i++) { g_rowstart[i] = run; run += g_degi[i]; }
    if (t == 1023) g_rowstart[N_NODES] = sh[1023];
}

__global__ void k_fill(const void* __restrict__ ei) {
    for (int e = blockIdx.x * blockDim.x + threadIdx.x; e < N_EDGES;
         e += gridDim.x * blockDim.x) {
        int d = edge_at(ei, (long long)N_EDGES + e);
        int s = edge_at(ei, e);
        int pos = atomicAdd(&g_cursor[d], 1);
        g_csrc[g_rowstart[d] + pos] = s;
    }
}

// -------------------- layer-1 mean aggregation (warp per node) --------------------

__global__ void k_aggr1(const float* __restrict__ x) {
    int warp = (blockIdx.x * blockDim.x + threadIdx.x) >> 5;
    if (warp >= N_NODES) return;
    int lane = threadIdx.x & 31;
    int rs = g_rowstart[warp], re = g_rowstart[warp + 1];
    float4 acc = make_float4(0.f, 0.f, 0.f, 0.f);
    for (int i0 = rs; i0 < re; i0 += 32) {
        int nv = min(32, re - i0);
        int s = (lane < nv) ? g_csrc[i0 + lane] : 0;
        for (int j = 0; j < nv; j++) {
            int sj = __shfl_sync(0xffffffffu, s, j);
            float4 v = *(const float4*)(x + (size_t)sj * IN_CH + lane * 4);
            acc.x += v.x; acc.y += v.y; acc.z += v.z; acc.w += v.w;
        }
    }
    float inv = 1.0f / fmaxf((float)(re - rs), 1.0f);
    acc.x *= inv; acc.y *= inv; acc.z *= inv; acc.w *= inv;
    *(float4*)(g_aggr1 + (size_t)warp * IN_CH + lane * 4) = acc;
}

// -------------------- GEMM 1: h = relu(aggr@Wl1 + b1 + x@Wr1) --------------------
// 256 threads, 32-node tile. thread t: out channel j=t&127, node half t>>7 (16 nodes).

__global__ __launch_bounds__(256) void k_gemm1(
    const float* __restrict__ x, const float* __restrict__ Wl1,
    const float* __restrict__ b1, const float* __restrict__ Wr1) {
    __shared__ float As[32 * 128];
    __shared__ float Xs[32 * 128];
    int node0 = blockIdx.x * 32;
    int t = threadIdx.x;
    for (int idx = t; idx < 1024; idx += 256) {
        int row = idx >> 5, col = idx & 31;
        ((float4*)As)[row * 32 + col] =
            ((const float4*)(g_aggr1 + (size_t)(node0 + row) * 128))[col];
        ((float4*)Xs)[row * 32 + col] =
            ((const float4*)(x + (size_t)(node0 + row) * 128))[col];
    }
    __syncthreads();

    int j = t & 127, half = t >> 7;
    float acc[16];
#pragma unroll
    for (int m = 0; m < 16; m++) acc[m] = 0.f;
    const float4* As4 = (const float4*)As + half * 16 * 32;
    const float4* Xs4 = (const float4*)Xs + half * 16 * 32;

    for (int k4 = 0; k4 < 32; k4++) {
        float wl0 = Wl1[(k4 * 4 + 0) * 128 + j];
        float wl1 = Wl1[(k4 * 4 + 1) * 128 + j];
        float wl2 = Wl1[(k4 * 4 + 2) * 128 + j];
        float wl3 = Wl1[(k4 * 4 + 3) * 128 + j];
        float wr0 = Wr1[(k4 * 4 + 0) * 128 + j];
        float wr1 = Wr1[(k4 * 4 + 1) * 128 + j];
        float wr2 = Wr1[(k4 * 4 + 2) * 128 + j];
        float wr3 = Wr1[(k4 * 4 + 3) * 128 + j];
#pragma unroll
        for (int m = 0; m < 16; m++) {
            float4 a = As4[m * 32 + k4];
            float4 xv = Xs4[m * 32 + k4];
            acc[m] += a.x * wl0 + a.y * wl1 + a.z * wl2 + a.w * wl3
                    + xv.x * wr0 + xv.y * wr1 + xv.z * wr2 + xv.w * wr3;
        }
    }
    float bb = b1[j];
#pragma unroll
    for (int m = 0; m < 16; m++) {
        g_h[(size_t)(node0 + half * 16 + m) * 128 + j] = fmaxf(acc[m] + bb, 0.f);
    }
}

// -------------------- GEMM 2: pq = h @ [Wl2 | Wr2]  (N x 80) --------------------
// 160 threads, 32-node tile. j = t%80 (j<40 -> Wl2/p, j>=40 -> Wr2/q), half = t/80.

__global__ __launch_bounds__(160) void k_gemm2(
    const float* __restrict__ Wl2, const float* __restrict__ Wr2) {
    __shared__ float Hs[32 * 128];
    int node0 = blockIdx.x * 32;
    int t = threadIdx.x;
    for (int idx = t; idx < 1024; idx += 160) {
        int row = idx >> 5, col = idx & 31;
        ((float4*)Hs)[row * 32 + col] =
            ((const float4*)(g_h + (size_t)(node0 + row) * 128))[col];
    }
    __syncthreads();

    int j = t % 80, half = t / 80;
    const float* W = (j < 40) ? Wl2 : Wr2;
    int jj = (j < 40) ? j : j - 40;
    float acc[16];
#pragma unroll
    for (int m = 0; m < 16; m++) acc[m] = 0.f;
    const float4* Hs4 = (const float4*)Hs + half * 16 * 32;

    for (int k4 = 0; k4 < 32; k4++) {
        float w0 = W[(k4 * 4 + 0) * 40 + jj];
        float w1 = W[(k4 * 4 + 1) * 40 + jj];
        float w2 = W[(k4 * 4 + 2) * 40 + jj];
        float w3 = W[(k4 * 4 + 3) * 40 + jj];
#pragma unroll
        for (int m = 0; m < 16; m++) {
            float4 h = Hs4[m * 32 + k4];
            acc[m] += h.x * w0 + h.y * w1 + h.z * w2 + h.w * w3;
        }
    }
#pragma unroll
    for (int m = 0; m < 16; m++) {
        g_pq[(size_t)(node0 + half * 16 + m) * 80 + j] = acc[m];
    }
}

// ---------- layer-2 aggregation + bias + log_softmax, fused (warp per node) ----------

__global__ void k_final(const float* __restrict__ b2, float* __restrict__ out) {
    int warp = (blockIdx.x * blockDim.x + threadIdx.x) >> 5;
    if (warp >= N_NODES) return;
    int lane = threadIdx.x & 31;
    int rs = g_rowstart[warp], re = g_rowstart[warp + 1];
    float acc0 = 0.f, acc1 = 0.f;
    for (int i0 = rs; i0 < re; i0 += 32) {
        int nv = min(32, re - i0);
        int s = (lane < nv) ? g_csrc[i0 + lane] : 0;
        for (int j = 0; j < nv; j++) {
            int sj = __shfl_sync(0xffffffffu, s, j);
            const float* pr = g_pq + (size_t)sj * 80;
            acc0 += pr[lane];
            if (lane < 8) acc1 += pr[32 + lane];
        }
    }
    float inv = 1.0f / fmaxf((float)(re - rs), 1.0f);
    const float* qr = g_pq + (size_t)warp * 80 + 40;
    float v0 = acc0 * inv + b2[lane] + qr[lane];
    float v1 = (lane < 8) ? (acc1 * inv + b2[32 + lane] + qr[32 + lane]) : -INFINITY;

    float mx = fmaxf(v0, v1);
#pragma unroll
    for (int o = 16; o; o >>= 1) mx = fmaxf(mx, __shfl_xor_sync(0xffffffffu, mx, o));
    float se = expf(v0 - mx) + ((lane < 8) ? expf(v1 - mx) : 0.f);
#pragma unroll
    for (int o = 16; o; o >>= 1) se += __shfl_xor_sync(0xffffffffu, se, o);
    float lse = logf(se);

    out[(size_t)warp * 40 + lane] = v0 - mx - lse;
    if (lane < 8) out[(size_t)warp * 40 + 32 + lane] = v1 - mx - lse;
}

// -------------------- launch --------------------

extern "C" void kernel_launch(void* const* d_in, const int* in_sizes, int n_in,
                              void* d_out, int out_size) {
    const float* x       = (const float*)d_in[0];
    const void*  ei      = d_in[1];
    const float* Wl1     = (const float*)d_in[2];
    const float* b1      = (const float*)d_in[3];
    const float* Wr1     = (const float*)d_in[4];
    const float* Wl2     = (const float*)d_in[5];
    const float* b2      = (const float*)d_in[6];
    const float* Wr2     = (const float*)d_in[7];
    float* out           = (float*)d_out;

    k_detect<<<1, 256>>>((const int*)ei);
    k_zero2<<<(N_NODES + 255) / 256, 256>>>();
    k_count<<<2048, 256>>>(ei);
    k_scan<<<1, 1024>>>();
    k_fill<<<2048, 256>>>(ei);
    k_aggr1<<<(N_NODES * 32 + 255) / 256, 256>>>(x);
    k_gemm1<<<N_NODES / 32, 256>>>(x, Wl1, b1, Wr1);
    k_gemm2<<<N_NODES / 32, 160>>>(Wl2, Wr2);
    k_final<<<(N_NODES * 32 + 255) / 256, 256>>>(b2, out);
}

// round 3
// speedup vs baseline: 1.1998x; 1.1998x over previous
#include <cuda_runtime.h>
#include <math.h>

#define N_NODES 100000
#define N_EDGES 1600000
#define IN_CH 128
#define HID 128
#define OUT_CH 40
#define NB_SCAN ((N_NODES + 1023) / 1024)   // 98

// -------- scratch (static __device__ globals; no runtime alloc) ----------
__device__ int   g_is64;
__device__ int   g_degi[N_NODES];
__device__ int   g_cursor[N_NODES];
__device__ int   g_rowstart[N_NODES + 1];
__device__ int   g_bsum[NB_SCAN];
__device__ int   g_boff[NB_SCAN];
__device__ int   g_csrc[N_EDGES];
__device__ float g_aggr1[(size_t)N_NODES * IN_CH];   // mean-aggregated x
__device__ float g_h[(size_t)N_NODES * HID];         // layer-1 output (relu)
__device__ float g_pq[(size_t)N_NODES * 80];         // [p(40) | q(40)] per node

// edge accessor: works for int32 or int64 edge_index
__device__ __forceinline__ int edge_at(const void* ei, long long idx) {
    if (g_is64) return (int)((const long long*)ei)[idx];
    return ((const int*)ei)[idx];
}

// -------------------- dtype detect + zero --------------------
__global__ void k_detect(const int* __restrict__ ei32) {
    __shared__ int nz;
    if (threadIdx.x == 0) nz = 0;
    __syncthreads();
    if (ei32[2 * threadIdx.x + 1] != 0) atomicAdd(&nz, 1);
    __syncthreads();
    if (threadIdx.x == 0) g_is64 = (nz == 0) ? 1 : 0;
}

__global__ void k_zero2() {
    int i = blockIdx.x * blockDim.x + threadIdx.x;
    if (i < N_NODES) { g_degi[i] = 0; g_cursor[i] = 0; }
}

// -------------------- CSR build --------------------

__global__ void k_count(const void* __restrict__ ei) {
    for (int e = blockIdx.x * blockDim.x + threadIdx.x; e < N_EDGES;
         e += gridDim.x * blockDim.x) {
        int d = edge_at(ei, (long long)N_EDGES + e);
        atomicAdd(&g_degi[d], 1);
    }
}

// ---- 3-phase multi-block exclusive scan of g_degi into g_rowstart ----

// phase 1: per-block scan; write block-partial exclusive prefix + block total
__global__ __launch_bounds__(1024) void k_scan1() {
    __shared__ int wsum[32];
    int i = blockIdx.x * 1024 + threadIdx.x;
    int lane = threadIdx.x & 31, wid = threadIdx.x >> 5;
    int v = (i < N_NODES) ? g_degi[i] : 0;
    int pre = v;
#pragma unroll
    for (int o = 1; o < 32; o <<= 1) {
        int t = __shfl_up_sync(0xffffffffu, pre, o);
        if (lane >= o) pre += t;
    }
    if (lane == 31) wsum[wid] = pre;
    __syncthreads();
    if (wid == 0) {
        int w = wsum[lane];
        int p = w;
#pragma unroll
        for (int o = 1; o < 32; o <<= 1) {
            int t = __shfl_up_sync(0xffffffffu, p, o);
            if (lane >= o) p += t;
        }
        wsum[lane] = p - w;                       // exclusive warp offset
        if (lane == 31) g_bsum[blockIdx.x] = p;   // block total
    }
    __syncthreads();
    if (i < N_NODES) g_rowstart[i] = pre - v + wsum[wid];
}

// phase 2: single tiny block scans the 98 block totals (exclusive)
__global__ void k_scan2() {
    int t = threadIdx.x;            // 128 threads
    int lane = t & 31, wid = t >> 5;
    __shared__ int ws[4];
    int v = (t < NB_SCAN) ? g_bsum[t] : 0;
    int pre = v;
#pragma unroll
    for (int o = 1; o < 32; o <<= 1) {
        int u = __shfl_up_sync(0xffffffffu, pre, o);
        if (lane >= o) pre += u;
    }
    if (lane == 31) ws[wid] = pre;
    __syncthreads();
    if (t == 0) {
        int r = 0;
#pragma unroll
        for (int k = 0; k < 4; k++) { int tmp = ws[k]; ws[k] = r; r += tmp; }
        g_rowstart[N_NODES] = N_EDGES;   // degrees always sum to N_EDGES
    }
    __syncthreads();
    if (t < NB_SCAN) g_boff[t] = pre - v + ws[wid];
}

// phase 3: add block offsets
__global__ __launch_bounds__(1024) void k_scan3() {
    int i = blockIdx.x * 1024 + threadIdx.x;
    if (i < N_NODES) g_rowstart[i] += g_boff[blockIdx.x];
}

__global__ void k_fill(const void* __restrict__ ei) {
    for (int e = blockIdx.x * blockDim.x + threadIdx.x; e < N_EDGES;
         e += gridDim.x * blockDim.x) {
        int d = edge_at(ei, (long long)N_EDGES + e);
        int s = edge_at(ei, e);
        int pos = atomicAdd(&g_cursor[d], 1);
        g_csrc[g_rowstart[d] + pos] = s;
    }
}

// -------------------- layer-1 mean aggregation (warp per node) --------------------

__global__ void k_aggr1(const float* __restrict__ x) {
    int warp = (blockIdx.x * blockDim.x + threadIdx.x) >> 5;
    if (warp >= N_NODES) return;
    int lane = threadIdx.x & 31;
    int rs = g_rowstart[warp], re = g_rowstart[warp + 1];
    float4 acc = make_float4(0.f, 0.f, 0.f, 0.f);
    for (int i0 = rs; i0 < re; i0 += 32) {
        int nv = min(32, re - i0);
        int s = (lane < nv) ? g_csrc[i0 + lane] : 0;
        for (int j = 0; j < nv; j++) {
            int sj = __shfl_sync(0xffffffffu, s, j);
            float4 v = *(const float4*)(x + (size_t)sj * IN_CH + lane * 4);
            acc.x += v.x; acc.y += v.y; acc.z += v.z; acc.w += v.w;
        }
    }
    float inv = 1.0f / fmaxf((float)(re - rs), 1.0f);
    acc.x *= inv; acc.y *= inv; acc.z *= inv; acc.w *= inv;
    *(float4*)(g_aggr1 + (size_t)warp * IN_CH + lane * 4) = acc;
}

// -------------------- GEMM 1: h = relu(aggr@Wl1 + b1 + x@Wr1) --------------------

__global__ __launch_bounds__(256) void k_gemm1(
    const float* __restrict__ x, const float* __restrict__ Wl1,
    const float* __restrict__ b1, const float* __restrict__ Wr1) {
    __shared__ float As[32 * 128];
    __shared__ float Xs[32 * 128];
    int node0 = blockIdx.x * 32;
    int t = threadIdx.x;
    for (int idx = t; idx < 1024; idx += 256) {
        int row = idx >> 5, col = idx & 31;
        ((float4*)As)[row * 32 + col] =
            ((const float4*)(g_aggr1 + (size_t)(node0 + row) * 128))[col];
        ((float4*)Xs)[row * 32 + col] =
            ((const float4*)(x + (size_t)(node0 + row) * 128))[col];
    }
    __syncthreads();

    int j = t & 127, half = t >> 7;
    float acc[16];
#pragma unroll
    for (int m = 0; m < 16; m++) acc[m] = 0.f;
    const float4* As4 = (const float4*)As + half * 16 * 32;
    const float4* Xs4 = (const float4*)Xs + half * 16 * 32;

    for (int k4 = 0; k4 < 32; k4++) {
        float wl0 = Wl1[(k4 * 4 + 0) * 128 + j];
        float wl1 = Wl1[(k4 * 4 + 1) * 128 + j];
        float wl2 = Wl1[(k4 * 4 + 2) * 128 + j];
        float wl3 = Wl1[(k4 * 4 + 3) * 128 + j];
        float wr0 = Wr1[(k4 * 4 + 0) * 128 + j];
        float wr1 = Wr1[(k4 * 4 + 1) * 128 + j];
        float wr2 = Wr1[(k4 * 4 + 2) * 128 + j];
        float wr3 = Wr1[(k4 * 4 + 3) * 128 + j];
#pragma unroll
        for (int m = 0; m < 16; m++) {
            float4 a = As4[m * 32 + k4];
            float4 xv = Xs4[m * 32 + k4];
            acc[m] += a.x * wl0 + a.y * wl1 + a.z * wl2 + a.w * wl3
                    + xv.x * wr0 + xv.y * wr1 + xv.z * wr2 + xv.w * wr3;
        }
    }
    float bb = b1[j];
#pragma unroll
    for (int m = 0; m < 16; m++) {
        g_h[(size_t)(node0 + half * 16 + m) * 128 + j] = fmaxf(acc[m] + bb, 0.f);
    }
}

// -------------------- GEMM 2: pq = h @ [Wl2 | Wr2]  (N x 80) --------------------

__global__ __launch_bounds__(160) void k_gemm2(
    const float* __restrict__ Wl2, const float* __restrict__ Wr2) {
    __shared__ float Hs[32 * 128];
    int node0 = blockIdx.x * 32;
    int t = threadIdx.x;
    for (int idx = t; idx < 1024; idx += 160) {
        int row = idx >> 5, col = idx & 31;
        ((float4*)Hs)[row * 32 + col] =
            ((const float4*)(g_h + (size_t)(node0 + row) * 128))[col];
    }
    __syncthreads();

    int j = t % 80, half = t / 80;
    const float* W = (j < 40) ? Wl2 : Wr2;
    int jj = (j < 40) ? j : j - 40;
    float acc[16];
#pragma unroll
    for (int m = 0; m < 16; m++) acc[m] = 0.f;
    const float4* Hs4 = (const float4*)Hs + half * 16 * 32;

    for (int k4 = 0; k4 < 32; k4++) {
        float w0 = W[(k4 * 4 + 0) * 40 + jj];
        float w1 = W[(k4 * 4 + 1) * 40 + jj];
        float w2 = W[(k4 * 4 + 2) * 40 + jj];
        float w3 = W[(k4 * 4 + 3) * 40 + jj];
#pragma unroll
        for (int m = 0; m < 16; m++) {
            float4 h = Hs4[m * 32 + k4];
            acc[m] += h.x * w0 + h.y * w1 + h.z * w2 + h.w * w3;
        }
    }
#pragma unroll
    for (int m = 0; m < 16; m++) {
        g_pq[(size_t)(node0 + half * 16 + m) * 80 + j] = acc[m];
    }
}

// ---------- layer-2 aggregation + bias + log_softmax, fused (warp per node) ----------

__global__ void k_final(const float* __restrict__ b2, float* __restrict__ out) {
    int warp = (blockIdx.x * blockDim.x + threadIdx.x) >> 5;
    if (warp >= N_NODES) return;
    int lane = threadIdx.x & 31;
    int rs = g_rowstart[warp], re = g_rowstart[warp + 1];
    float acc0 = 0.f, acc1 = 0.f;
    for (int i0 = rs; i0 < re; i0 += 32) {
        int nv = min(32, re - i0);
        int s = (lane < nv) ? g_csrc[i0 + lane] : 0;
        for (int j = 0; j < nv; j++) {
            int sj = __shfl_sync(0xffffffffu, s, j);
            const float* pr = g_pq + (size_t)sj * 80;
            acc0 += pr[lane];
            if (lane < 8) acc1 += pr[32 + lane];
        }
    }
    float inv = 1.0f / fmaxf((float)(re - rs), 1.0f);
    const float* qr = g_pq + (size_t)warp * 80 + 40;
    float v0 = acc0 * inv + b2[lane] + qr[lane];
    float v1 = (lane < 8) ? (acc1 * inv + b2[32 + lane] + qr[32 + lane]) : -INFINITY;

    float mx = fmaxf(v0, v1);
#pragma unroll
    for (int o = 16; o; o >>= 1) mx = fmaxf(mx, __shfl_xor_sync(0xffffffffu, mx, o));
    float se = expf(v0 - mx) + ((lane < 8) ? expf(v1 - mx) : 0.f);
#pragma unroll
    for (int o = 16; o; o >>= 1) se += __shfl_xor_sync(0xffffffffu, se, o);
    float lse = logf(se);

    out[(size_t)warp * 40 + lane] = v0 - mx - lse;
    if (lane < 8) out[(size_t)warp * 40 + 32 + lane] = v1 - mx - lse;
}

// -------------------- launch --------------------

extern "C" void kernel_launch(void* const* d_in, const int* in_sizes, int n_in,
                              void* d_out, int out_size) {
    const float* x       = (const float*)d_in[0];
    const void*  ei      = d_in[1];
    const float* Wl1     = (const float*)d_in[2];
    const float* b1      = (const float*)d_in[3];
    const float* Wr1     = (const float*)d_in[4];
    const float* Wl2     = (const float*)d_in[5];
    const float* b2      = (const float*)d_in[6];
    const float* Wr2     = (const float*)d_in[7];
    float* out           = (float*)d_out;

    k_detect<<<1, 256>>>((const int*)ei);
    k_zero2<<<(N_NODES + 255) / 256, 256>>>();
    k_count<<<2048, 256>>>(ei);
    k_scan1<<<NB_SCAN, 1024>>>();
    k_scan2<<<1, 128>>>();
    k_scan3<<<NB_SCAN, 1024>>>();
    k_fill<<<2048, 256>>>(ei);
    k_aggr1<<<(N_NODES * 32 + 255) / 256, 256>>>(x);
    k_gemm1<<<N_NODES / 32, 256>>>(x, Wl1, b1, Wr1);
    k_gemm2<<<N_NODES / 32, 160>>>(Wl2, Wr2);
    k_final<<<(N_NODES * 32 + 255) / 256, 256>>>(b2, out);
}

// round 5
// speedup vs baseline: 1.5327x; 1.2774x over previous
#include <cuda_runtime.h>
#include <cuda_bf16.h>
#include <mma.h>
#include <math.h>
#include <cstdint>

using namespace nvcuda;

#define N_NODES 100000
#define N_EDGES 1600000
#define IN_CH 128
#define HID 128
#define OUT_CH 40
#define NB_SCAN ((N_NODES + 1023) / 1024)   // 98

#define TS 136                               // smem tile stride (elements)
#define TILE_ELEMS (128 * TS)
#define GEMM1_SMEM (4 * TILE_ELEMS * 2)      // 4 bf16 tiles: Ah, Al, Wh, Wl

// -------- scratch (static __device__ globals; no runtime alloc) ----------
__device__ int   g_is64;
__device__ int   g_degi[N_NODES];
__device__ int   g_cursor[N_NODES];
__device__ int   g_rowstart[N_NODES + 1];
__device__ int   g_bsum[NB_SCAN];
__device__ int   g_boff[NB_SCAN];
__device__ int   g_csrc[N_EDGES];
__device__ float g_aggr1[(size_t)N_NODES * IN_CH];   // mean-aggregated x
__device__ float g_h[(size_t)N_NODES * HID];         // layer-1 output (relu)
__device__ float g_pq[(size_t)N_NODES * 80];         // [p(40) | q(40)] per node

// edge accessor: works for int32 or int64 edge_index
__device__ __forceinline__ int edge_at(const void* ei, long long idx) {
    if (g_is64) return (int)((const long long*)ei)[idx];
    return ((const int*)ei)[idx];
}

// -------------------- dtype detect + zero --------------------
__global__ void k_detect(const int* __restrict__ ei32) {
    __shared__ int nz;
    if (threadIdx.x == 0) nz = 0;
    __syncthreads();
    if (ei32[2 * threadIdx.x + 1] != 0) atomicAdd(&nz, 1);
    __syncthreads();
    if (threadIdx.x == 0) g_is64 = (nz == 0) ? 1 : 0;
}

__global__ void k_zero2() {
    int i = blockIdx.x * blockDim.x + threadIdx.x;
    if (i < N_NODES) { g_degi[i] = 0; g_cursor[i] = 0; }
}

// -------------------- CSR build --------------------

__global__ void k_count(const void* __restrict__ ei) {
    for (int e = blockIdx.x * blockDim.x + threadIdx.x; e < N_EDGES;
         e += gridDim.x * blockDim.x) {
        int d = edge_at(ei, (long long)N_EDGES + e);
        atomicAdd(&g_degi[d], 1);
    }
}

__global__ __launch_bounds__(1024) void k_scan1() {
    __shared__ int wsum[32];
    int i = blockIdx.x * 1024 + threadIdx.x;
    int lane = threadIdx.x & 31, wid = threadIdx.x >> 5;
    int v = (i < N_NODES) ? g_degi[i] : 0;
    int pre = v;
#pragma unroll
    for (int o = 1; o < 32; o <<= 1) {
        int t = __shfl_up_sync(0xffffffffu, pre, o);
        if (lane >= o) pre += t;
    }
    if (lane == 31) wsum[wid] = pre;
    __syncthreads();
    if (wid == 0) {
        int w = wsum[lane];
        int p = w;
#pragma unroll
        for (int o = 1; o < 32; o <<= 1) {
            int t = __shfl_up_sync(0xffffffffu, p, o);
            if (lane >= o) p += t;
        }
        wsum[lane] = p - w;
        if (lane == 31) g_bsum[blockIdx.x] = p;
    }
    __syncthreads();
    if (i < N_NODES) g_rowstart[i] = pre - v + wsum[wid];
}

__global__ void k_scan2() {
    int t = threadIdx.x;            // 128 threads
    int lane = t & 31, wid = t >> 5;
    __shared__ int ws[4];
    int v = (t < NB_SCAN) ? g_bsum[t] : 0;
    int pre = v;
#pragma unroll
    for (int o = 1; o < 32; o <<= 1) {
        int u = __shfl_up_sync(0xffffffffu, pre, o);
        if (lane >= o) pre += u;
    }
    if (lane == 31) ws[wid] = pre;
    __syncthreads();
    if (t == 0) {
        int r = 0;
#pragma unroll
        for (int k = 0; k < 4; k++) { int tmp = ws[k]; ws[k] = r; r += tmp; }
        g_rowstart[N_NODES] = N_EDGES;
    }
    __syncthreads();
    if (t < NB_SCAN) g_boff[t] = pre - v + ws[wid];
}

__global__ __launch_bounds__(1024) void k_scan3() {
    int i = blockIdx.x * 1024 + threadIdx.x;
    if (i < N_NODES) g_rowstart[i] += g_boff[blockIdx.x];
}

__global__ void k_fill(const void* __restrict__ ei) {
    for (int e = blockIdx.x * blockDim.x + threadIdx.x; e < N_EDGES;
         e += gridDim.x * blockDim.x) {
        int d = edge_at(ei, (long long)N_EDGES + e);
        int s = edge_at(ei, e);
        int pos = atomicAdd(&g_cursor[d], 1);
        g_csrc[g_rowstart[d] + pos] = s;
    }
}

// -------------------- layer-1 mean aggregation (warp per node) --------------------

__global__ void k_aggr1(const float* __restrict__ x) {
    int warp = (blockIdx.x * blockDim.x + threadIdx.x) >> 5;
    if (warp >= N_NODES) return;
    int lane = threadIdx.x & 31;
    int rs = g_rowstart[warp], re = g_rowstart[warp + 1];
    float4 acc = make_float4(0.f, 0.f, 0.f, 0.f);
    for (int i0 = rs; i0 < re; i0 += 32) {
        int nv = min(32, re - i0);
        int s = (lane < nv) ? g_csrc[i0 + lane] : 0;
        for (int j = 0; j < nv; j++) {
            int sj = __shfl_sync(0xffffffffu, s, j);
            float4 v = *(const float4*)(x + (size_t)sj * IN_CH + lane * 4);
            acc.x += v.x; acc.y += v.y; acc.z += v.z; acc.w += v.w;
        }
    }
    float inv = 1.0f / fmaxf((float)(re - rs), 1.0f);
    acc.x *= inv; acc.y *= inv; acc.z *= inv; acc.w *= inv;
    *(float4*)(g_aggr1 + (size_t)warp * IN_CH + lane * 4) = acc;
}

// ============ GEMM 1 via wmma bf16 split: h = relu(aggr@Wl1 + x@Wr1 + b1) ============
// Per CTA: 128 nodes x 128 out ch, K=128. 8 warps, each 32x64 of output.
// Split-bf16 compensation: A@W ~= Ah@Wh + Al@Wh + Ah@Wl (drop Al@Wl, ~2^-32).

// convert 4 fp32 -> 4 hi bf16 + 4 lo bf16 (packed as uint2 each)
__device__ __forceinline__ void split4(float4 v, uint2& hi, uint2& lo) {
    __nv_bfloat162 h01 = __floats2bfloat162_rn(v.x, v.y);
    __nv_bfloat162 h23 = __floats2bfloat162_rn(v.z, v.w);
    float r0 = v.x - __low2float(h01),  r1 = v.y - __high2float(h01);
    float r2 = v.z - __low2float(h23),  r3 = v.w - __high2float(h23);
    __nv_bfloat162 l01 = __floats2bfloat162_rn(r0, r1);
    __nv_bfloat162 l23 = __floats2bfloat162_rn(r2, r3);
    hi = make_uint2(*(uint32_t*)&h01, *(uint32_t*)&h23);
    lo = make_uint2(*(uint32_t*)&l01, *(uint32_t*)&l23);
}

// convert a 128-row x 128-col fp32 matrix (row stride 128) into hi/lo smem tiles
__device__ __forceinline__ void conv_tile(const float* __restrict__ src, int row0,
                                          int row_clamp, __nv_bfloat16* H,
                                          __nv_bfloat16* L, int tid) {
    for (int g = tid; g < 4096; g += 256) {
        int row = g >> 5, c4 = g & 31;
        int r = row0 + row;
        if (r >= row_clamp) r = row_clamp - 1;
        float4 v = ((const float4*)(src + (size_t)r * 128))[c4];
        uint2 hi, lo;
        split4(v, hi, lo);
        *(uint2*)(H + row * TS + c4 * 4) = hi;
        *(uint2*)(L + row * TS + c4 * 4) = lo;
    }
}

__global__ __launch_bounds__(256) void k_gemm1_mma(
    const float* __restrict__ x, const float* __restrict__ Wl1,
    const float* __restrict__ b1, const float* __restrict__ Wr1) {
    extern __shared__ __nv_bfloat16 sm[];
    __nv_bfloat16* AH = sm;
    __nv_bfloat16* AL = sm + TILE_ELEMS;
    __nv_bfloat16* WH = sm + 2 * TILE_ELEMS;
    __nv_bfloat16* WL = sm + 3 * TILE_ELEMS;

    int tid = threadIdx.x;
    int wid = tid >> 5, lane = tid & 31;
    int node0 = blockIdx.x * 128;
    int wm = wid & 3;        // m tile: rows wm*32 .. +31
    int wn = wid >> 2;       // n tile: cols wn*64 .. +63

    wmma::fragment<wmma::accumulator, 16, 16, 16, float> C[2][4];
#pragma unroll
    for (int i = 0; i < 2; i++)
#pragma unroll
        for (int j = 0; j < 4; j++) wmma::fill_fragment(C[i][j], 0.0f);

#pragma unroll
    for (int phase = 0; phase < 2; phase++) {
        const float* Asrc = phase ? x : g_aggr1;
        const float* Wsrc = phase ? Wr1 : Wl1;
        conv_tile(Asrc, node0, N_NODES, AH, AL, tid);
        conv_tile(Wsrc, 0, 128, WH, WL, tid);
        __syncthreads();

#pragma unroll
        for (int k0 = 0; k0 < 8; k0++) {
            wmma::fragment<wmma::matrix_a, 16, 16, 16, __nv_bfloat16, wmma::row_major> ah[2], al[2];
            wmma::fragment<wmma::matrix_b, 16, 16, 16, __nv_bfloat16, wmma::row_major> bh[4], bl[4];
#pragma unroll
            for (int i = 0; i < 2; i++) {
                const __nv_bfloat16* ap = AH + (wm * 32 + i * 16) * TS + k0 * 16;
                const __nv_bfloat16* lp = AL + (wm * 32 + i * 16) * TS + k0 * 16;
                wmma::load_matrix_sync(ah[i], ap, TS);
                wmma::load_matrix_sync(al[i], lp, TS);
            }
#pragma unroll
            for (int j = 0; j < 4; j++) {
                const __nv_bfloat16* bp = WH + (k0 * 16) * TS + wn * 64 + j * 16;
                const __nv_bfloat16* qp = WL + (k0 * 16) * TS + wn * 64 + j * 16;
                wmma::load_matrix_sync(bh[j], bp, TS);
                wmma::load_matrix_sync(bl[j], qp, TS);
            }
#pragma unroll
            for (int i = 0; i < 2; i++)
#pragma unroll
                for (int j = 0; j < 4; j++) {
                    wmma::mma_sync(C[i][j], ah[i], bh[j], C[i][j]);
                    wmma::mma_sync(C[i][j], al[i], bh[j], C[i][j]);
                    wmma::mma_sync(C[i][j], ah[i], bl[j], C[i][j]);
                }
        }
        __syncthreads();   // protect smem before next-phase overwrite
    }

    // ---- epilogue: dump acc frags to smem (reused), add bias, relu, store ----
    float* eb = (float*)sm + (size_t)wid * 2048;   // 32x64 fp32 per warp
#pragma unroll
    for (int i = 0; i < 2; i++)
#pragma unroll
        for (int j = 0; j < 4; j++)
            wmma::store_matrix_sync(eb + i * 16 * 64 + j * 16, C[i][j], 64,
                                    wmma::mem_row_major);
    __syncwarp();

    for (int e = lane; e < 512; e += 32) {       // 512 float4 per warp region
        int r = e >> 4, c4 = e & 15;
        int node = node0 + wm * 32 + r;
        if (node >= N_NODES) continue;
        int col = wn * 64 + c4 * 4;
        float4 v = ((float4*)eb)[e];
        float4 bb = *(const float4*)(b1 + col);
        float4 o;
        o.x = fmaxf(v.x + bb.x, 0.f);
        o.y = fmaxf(v.y + bb.y, 0.f);
        o.z = fmaxf(v.z + bb.z, 0.f);
        o.w = fmaxf(v.w + bb.w, 0.f);
        *(float4*)(g_h + (size_t)node * 128 + col) = o;
    }
}

// -------------------- GEMM 2: pq = h @ [Wl2 | Wr2]  (N x 80) --------------------

__global__ __launch_bounds__(160) void k_gemm2(
    const float* __restrict__ Wl2, const float* __restrict__ Wr2) {
    __shared__ float Hs[32 * 128];
    int node0 = blockIdx.x * 32;
    int t = threadIdx.x;
    for (int idx = t; idx < 1024; idx += 160) {
        int row = idx >> 5, col = idx & 31;
        ((float4*)Hs)[row * 32 + col] =
            ((const float4*)(g_h + (size_t)(node0 + row) * 128))[col];
    }
    __syncthreads();

    int j = t % 80, half = t / 80;
    const float* W = (j < 40) ? Wl2 : Wr2;
    int jj = (j < 40) ? j : j - 40;
    float acc[16];
#pragma unroll
    for (int m = 0; m < 16; m++) acc[m] = 0.f;
    const float4* Hs4 = (const float4*)Hs + half * 16 * 32;

    for (int k4 = 0; k4 < 32; k4++) {
        float w0 = W[(k4 * 4 + 0) * 40 + jj];
        float w1 = W[(k4 * 4 + 1) * 40 + jj];
        float w2 = W[(k4 * 4 + 2) * 40 + jj];
        float w3 = W[(k4 * 4 + 3) * 40 + jj];
#pragma unroll
        for (int m = 0; m < 16; m++) {
            float4 h = Hs4[m * 32 + k4];
            acc[m] += h.x * w0 + h.y * w1 + h.z * w2 + h.w * w3;
        }
    }
#pragma unroll
    for (int m = 0; m < 16; m++) {
        g_pq[(size_t)(node0 + half * 16 + m) * 80 + j] = acc[m];
    }
}

// ---------- layer-2 aggregation + bias + log_softmax, fused (warp per node) ----------

__global__ void k_final(const float* __restrict__ b2, float* __restrict__ out) {
    int warp = (blockIdx.x * blockDim.x + threadIdx.x) >> 5;
    if (warp >= N_NODES) return;
    int lane = threadIdx.x & 31;
    int rs = g_rowstart[warp], re = g_rowstart[warp + 1];
    float acc0 = 0.f, acc1 = 0.f;
    for (int i0 = rs; i0 < re; i0 += 32) {
        int nv = min(32, re - i0);
        int s = (lane < nv) ? g_csrc[i0 + lane] : 0;
        for (int j = 0; j < nv; j++) {
            int sj = __shfl_sync(0xffffffffu, s, j);
            const float* pr = g_pq + (size_t)sj * 80;
            acc0 += pr[lane];
            if (lane < 8) acc1 += pr[32 + lane];
        }
    }
    float inv = 1.0f / fmaxf((float)(re - rs), 1.0f);
    const float* qr = g_pq + (size_t)warp * 80 + 40;
    float v0 = acc0 * inv + b2[lane] + qr[lane];
    float v1 = (lane < 8) ? (acc1 * inv + b2[32 + lane] + qr[32 + lane]) : -INFINITY;

    float mx = fmaxf(v0, v1);
#pragma unroll
    for (int o = 16; o; o >>= 1) mx = fmaxf(mx, __shfl_xor_sync(0xffffffffu, mx, o));
    float se = expf(v0 - mx) + ((lane < 8) ? expf(v1 - mx) : 0.f);
#pragma unroll
    for (int o = 16; o; o >>= 1) se += __shfl_xor_sync(0xffffffffu, se, o);
    float lse = logf(se);

    out[(size_t)warp * 40 + lane] = v0 - mx - lse;
    if (lane < 8) out[(size_t)warp * 40 + 32 + lane] = v1 - mx - lse;
}

// -------------------- launch --------------------

extern "C" void kernel_launch(void* const* d_in, const int* in_sizes, int n_in,
                              void* d_out, int out_size) {
    const float* x       = (const float*)d_in[0];
    const void*  ei      = d_in[1];
    const float* Wl1     = (const float*)d_in[2];
    const float* b1      = (const float*)d_in[3];
    const float* Wr1     = (const float*)d_in[4];
    const float* Wl2     = (const float*)d_in[5];
    const float* b2      = (const float*)d_in[6];
    const float* Wr2     = (const float*)d_in[7];
    float* out           = (float*)d_out;

    // not a stream op; capture-safe and idempotent
    cudaFuncSetAttribute(k_gemm1_mma, cudaFuncAttributeMaxDynamicSharedMemorySize,
                         GEMM1_SMEM);

    k_detect<<<1, 256>>>((const int*)ei);
    k_zero2<<<(N_NODES + 255) / 256, 256>>>();
    k_count<<<2048, 256>>>(ei);
    k_scan1<<<NB_SCAN, 1024>>>();
    k_scan2<<<1, 128>>>();
    k_scan3<<<NB_SCAN, 1024>>>();
    k_fill<<<2048, 256>>>(ei);
    k_aggr1<<<(N_NODES * 32 + 255) / 256, 256>>>(x);
    k_gemm1_mma<<<(N_NODES + 127) / 128, 256, GEMM1_SMEM>>>(x, Wl1, b1, Wr1);
    k_gemm2<<<N_NODES / 32, 160>>>(Wl2, Wr2);
    k_final<<<(N_NODES * 32 + 255) / 256, 256>>>(b2, out);
}

// round 7
// speedup vs baseline: 1.5982x; 1.0428x over previous
#include <cuda_runtime.h>
#include <cuda_bf16.h>
#include <mma.h>
#include <math.h>
#include <cstdint>

using namespace nvcuda;

#define N_NODES 100000
#define N_EDGES 1600000
#define N_PAD 100096                          // 782*128
#define NB_SCAN ((N_NODES + 1023) / 1024)     // 98

#define TS 136                                // smem A/W tile stride (bf16 elems)
#define T2S 88                                // smem W2 tile stride
#define TILE_ELEMS (128 * TS)

// gemm1 smem: AH, AL, WLH, WLL, WRH, WRL  (6 x 128 x 136 bf16)
#define GEMM1_SMEM (6 * TILE_ELEMS * 2)
// gemm2 smem: AH, AL (128x136) + W2H, W2L (128x88)
#define GEMM2_SMEM ((2 * 128 * TS + 2 * 128 * T2S) * 2)

// -------- scratch (static __device__ globals; no runtime alloc) ----------
__device__ int   g_is64;
__device__ int   g_degi[N_NODES];
__device__ int   g_cursor[N_NODES];
__device__ int   g_rowstart[N_NODES + 1];
__device__ int   g_bsum[NB_SCAN];
__device__ int   g_boff[NB_SCAN];
__device__ int   g_csrc[N_EDGES];
__device__ float g_y1[(size_t)N_PAD * 128];   // x @ Wl1
__device__ float g_yr[(size_t)N_PAD * 128];   // x @ Wr1
__device__ float g_h[(size_t)N_NODES * 128];  // layer-1 output (relu)
__device__ float g_pq[(size_t)N_PAD * 80];    // [p(40) | q(40)] per node
// precomputed weight splits (bf16 hi/lo)
__device__ __nv_bfloat16 g_wl1h[16384], g_wl1l[16384];
__device__ __nv_bfloat16 g_wr1h[16384], g_wr1l[16384];
__device__ __nv_bfloat16 g_w2h[10240],  g_w2l[10240];   // [Wl2|Wr2] 128x80

// edge accessor: works for int32 or int64 edge_index
__device__ __forceinline__ int edge_at(const void* ei, long long idx) {
    if (g_is64) return (int)((const long long*)ei)[idx];
    return ((const int*)ei)[idx];
}

// -------------------- dtype detect + zero + weight prep --------------------
__global__ void k_detect(const int* __restrict__ ei32) {
    __shared__ int nz;
    if (threadIdx.x == 0) nz = 0;
    __syncthreads();
    if (ei32[2 * threadIdx.x + 1] != 0) atomicAdd(&nz, 1);
    __syncthreads();
    if (threadIdx.x == 0) g_is64 = (nz == 0) ? 1 : 0;
}

__global__ void k_zero2() {
    int i = blockIdx.x * blockDim.x + threadIdx.x;
    if (i < N_NODES) { g_degi[i] = 0; g_cursor[i] = 0; }
}

__device__ __forceinline__ void split1(float v, __nv_bfloat16& h, __nv_bfloat16& l) {
    h = __float2bfloat16_rn(v);
    l = __float2bfloat16_rn(v - __bfloat162float(h));
}

__global__ __launch_bounds__(1024) void k_prep_w(
    const float* __restrict__ Wl1, const float* __restrict__ Wr1,
    const float* __restrict__ Wl2, const float* __restrict__ Wr2) {
    for (int i = threadIdx.x; i < 16384; i += 1024) {
        split1(Wl1[i], g_wl1h[i], g_wl1l[i]);
        split1(Wr1[i], g_wr1h[i], g_wr1l[i]);
    }
    for (int i = threadIdx.x; i < 10240; i += 1024) {
        int k = i / 80, j = i % 80;
        float v = (j < 40) ? Wl2[k * 40 + j] : Wr2[k * 40 + (j - 40)];
        split1(v, g_w2h[i], g_w2l[i]);
    }
}

// -------------------- CSR build --------------------

__global__ void k_count(const void* __restrict__ ei) {
    for (int e = blockIdx.x * blockDim.x + threadIdx.x; e < N_EDGES;
         e += gridDim.x * blockDim.x) {
        int d = edge_at(ei, (long long)N_EDGES + e);
        atomicAdd(&g_degi[d], 1);
    }
}

__global__ __launch_bounds__(1024) void k_scan1() {
    __shared__ int wsum[32];
    int i = blockIdx.x * 1024 + threadIdx.x;
    int lane = threadIdx.x & 31, wid = threadIdx.x >> 5;
    int v = (i < N_NODES) ? g_degi[i] : 0;
    int pre = v;
#pragma unroll
    for (int o = 1; o < 32; o <<= 1) {
        int t = __shfl_up_sync(0xffffffffu, pre, o);
        if (lane >= o) pre += t;
    }
    if (lane == 31) wsum[wid] = pre;
    __syncthreads();
    if (wid == 0) {
        int w = wsum[lane];
        int p = w;
#pragma unroll
        for (int o = 1; o < 32; o <<= 1) {
            int t = __shfl_up_sync(0xffffffffu, p, o);
            if (lane >= o) p += t;
        }
        wsum[lane] = p - w;
        if (lane == 31) g_bsum[blockIdx.x] = p;
    }
    __syncthreads();
    if (i < N_NODES) g_rowstart[i] = pre - v + wsum[wid];
}

__global__ void k_scan2() {
    int t = threadIdx.x;            // 128 threads
    int lane = t & 31, wid = t >> 5;
    __shared__ int ws[4];
    int v = (t < NB_SCAN) ? g_bsum[t] : 0;
    int pre = v;
#pragma unroll
    for (int o = 1; o < 32; o <<= 1) {
        int u = __shfl_up_sync(0xffffffffu, pre, o);
        if (lane >= o) pre += u;
    }
    if (lane == 31) ws[wid] = pre;
    __syncthreads();
    if (t == 0) {
        int r = 0;
#pragma unroll
        for (int k = 0; k < 4; k++) { int tmp = ws[k]; ws[k] = r; r += tmp; }
        g_rowstart[N_NODES] = N_EDGES;
    }
    __syncthreads();
    if (t < NB_SCAN) g_boff[t] = pre - v + ws[wid];
}

__global__ __launch_bounds__(1024) void k_scan3() {
    int i = blockIdx.x * 1024 + threadIdx.x;
    if (i < N_NODES) g_rowstart[i] += g_boff[blockIdx.x];
}

__global__ void k_fill(const void* __restrict__ ei) {
    for (int e = blockIdx.x * blockDim.x + threadIdx.x; e < N_EDGES;
         e += gridDim.x * blockDim.x) {
        int d = edge_at(ei, (long long)N_EDGES + e);
        int s = edge_at(ei, e);
        int pos = atomicAdd(&g_cursor[d], 1);
        g_csrc[g_rowstart[d] + pos] = s;
    }
}

// ============ helpers for wmma GEMMs ============

// convert 4 fp32 -> hi/lo packed bf16x2 pairs
__device__ __forceinline__ void split4(float4 v, uint2& hi, uint2& lo) {
    __nv_bfloat162 h01 = __floats2bfloat162_rn(v.x, v.y);
    __nv_bfloat162 h23 = __floats2bfloat162_rn(v.z, v.w);
    float r0 = v.x - __low2float(h01),  r1 = v.y - __high2float(h01);
    float r2 = v.z - __low2float(h23),  r3 = v.w - __high2float(h23);
    __nv_bfloat162 l01 = __floats2bfloat162_rn(r0, r1);
    __nv_bfloat162 l23 = __floats2bfloat162_rn(r2, r3);
    hi = make_uint2(*(uint32_t*)&h01, *(uint32_t*)&h23);
    lo = make_uint2(*(uint32_t*)&l01, *(uint32_t*)&l23);
}

// convert 128x128 fp32 (row stride 128, rows clamped) into hi/lo smem tiles
template <int NTHREADS>
__device__ __forceinline__ void conv_tile(const float* __restrict__ src, int row0,
                                          __nv_bfloat16* H, __nv_bfloat16* L, int tid) {
    for (int g = tid; g < 4096; g += NTHREADS) {
        int row = g >> 5, c4 = g & 31;
        int r = row0 + row;
        if (r >= N_NODES) r = N_NODES - 1;
        float4 v = ((const float4*)(src + (size_t)r * 128))[c4];
        uint2 hi, lo;
        split4(v, hi, lo);
        *(uint2*)(H + row * TS + c4 * 4) = hi;
        *(uint2*)(L + row * TS + c4 * 4) = lo;
    }
}

// ============ GEMM 1: y1 = x@Wl1, yr = x@Wr1 (single A conversion) ============
// 512 threads. Warps 0-7 -> y1 (weights WL), warps 8-15 -> yr (weights WR).
// Each warp: 32 rows x 64 cols. Split-bf16: A@W ~= Ah@Wh + Al@Wh + Ah@Wl.

__global__ __launch_bounds__(512) void k_gemm1(const float* __restrict__ x) {
    extern __shared__ __nv_bfloat16 sm[];
    __nv_bfloat16* AH  = sm;
    __nv_bfloat16* AL  = sm + TILE_ELEMS;
    __nv_bfloat16* WH0 = sm + 2 * TILE_ELEMS;  // WL hi
    __nv_bfloat16* WL0 = sm + 3 * TILE_ELEMS;  // WL lo
    __nv_bfloat16* WH1 = sm + 4 * TILE_ELEMS;  // WR hi
    __nv_bfloat16* WL1 = sm + 5 * TILE_ELEMS;  // WR lo

    int tid = threadIdx.x;
    int wid = tid >> 5;
    int node0 = blockIdx.x * 128;

    // copy precomputed weight splits into padded smem (no math).
    // one uint4 = 8 bf16 elements; 16 uint4 per 128-elem row.
    {
        const __nv_bfloat16* srcs[4] = {g_wl1h, g_wl1l, g_wr1h, g_wr1l};
        __nv_bfloat16* dsts[4] = {WH0, WL0, WH1, WL1};
#pragma unroll
        for (int tgt = 0; tgt < 4; tgt++) {
            const uint4* s = (const uint4*)srcs[tgt];
            for (int g = tid; g < 2048; g += 512) {   // 128 rows x 16 uint4
                int row = g >> 4, c = g & 15;
                *(uint4*)(dsts[tgt] + row * TS + c * 8) = s[row * 16 + c];
            }
        }
    }
    conv_tile<512>(x, node0, AH, AL, tid);
    __syncthreads();

    int out_sel = wid >> 3;          // 0: y1, 1: yr
    int w = wid & 7;
    int wm = w & 3;                  // rows wm*32
    int wn = w >> 2;                 // cols wn*64
    const __nv_bfloat16* WH = out_sel ? WH1 : WH0;
    const __nv_bfloat16* WL = out_sel ? WL1 : WL0;

    wmma::fragment<wmma::accumulator, 16, 16, 16, float> C[2][4];
#pragma unroll
    for (int i = 0; i < 2; i++)
#pragma unroll
        for (int j = 0; j < 4; j++) wmma::fill_fragment(C[i][j], 0.0f);

#pragma unroll
    for (int k0 = 0; k0 < 8; k0++) {
        wmma::fragment<wmma::matrix_a, 16, 16, 16, __nv_bfloat16, wmma::row_major> ah[2], al[2];
#pragma unroll
        for (int i = 0; i < 2; i++) {
            wmma::load_matrix_sync(ah[i], AH + (wm * 32 + i * 16) * TS + k0 * 16, TS);
            wmma::load_matrix_sync(al[i], AL + (wm * 32 + i * 16) * TS + k0 * 16, TS);
        }
#pragma unroll
        for (int j = 0; j < 4; j++) {
            wmma::fragment<wmma::matrix_b, 16, 16, 16, __nv_bfloat16, wmma::row_major> bh, bl;
            wmma::load_matrix_sync(bh, WH + (k0 * 16) * TS + wn * 64 + j * 16, TS);
            wmma::load_matrix_sync(bl, WL + (k0 * 16) * TS + wn * 64 + j * 16, TS);
#pragma unroll
            for (int i = 0; i < 2; i++) {
                wmma::mma_sync(C[i][j], ah[i], bh, C[i][j]);
                wmma::mma_sync(C[i][j], al[i], bh, C[i][j]);
                wmma::mma_sync(C[i][j], ah[i], bl, C[i][j]);
            }
        }
    }

    // store fragments straight to (padded) global
    float* dst = (out_sel ? g_yr : g_y1) + (size_t)(node0 + wm * 32) * 128 + wn * 64;
#pragma unroll
    for (int i = 0; i < 2; i++)
#pragma unroll
        for (int j = 0; j < 4; j++)
            wmma::store_matrix_sync(dst + (size_t)i * 16 * 128 + j * 16, C[i][j],
                                    128, wmma::mem_row_major);
}

// ---------- h = relu(mean-gather(y1) + yr + b1)  (warp per node) ----------

__global__ void k_aggr_relu(const float* __restrict__ b1) {
    int warp = (blockIdx.x * blockDim.x + threadIdx.x) >> 5;
    if (warp >= N_NODES) return;
    int lane = threadIdx.x & 31;
    int rs = g_rowstart[warp], re = g_rowstart[warp + 1];
    float4 acc = make_float4(0.f, 0.f, 0.f, 0.f);
    for (int i0 = rs; i0 < re; i0 += 32) {
        int nv = min(32, re - i0);
        int s = (lane < nv) ? g_csrc[i0 + lane] : 0;
        for (int j = 0; j < nv; j++) {
            int sj = __shfl_sync(0xffffffffu, s, j);
            float4 v = *(const float4*)(g_y1 + (size_t)sj * 128 + lane * 4);
            acc.x += v.x; acc.y += v.y; acc.z += v.z; acc.w += v.w;
        }
    }
    float inv = 1.0f / fmaxf((float)(re - rs), 1.0f);
    float4 yr = *(const float4*)(g_yr + (size_t)warp * 128 + lane * 4);
    float4 bb = *(const float4*)(b1 + lane * 4);
    float4 o;
    o.x = fmaxf(acc.x * inv + yr.x + bb.x, 0.f);
    o.y = fmaxf(acc.y * inv + yr.y + bb.y, 0.f);
    o.z = fmaxf(acc.z * inv + yr.z + bb.z, 0.f);
    o.w = fmaxf(acc.w * inv + yr.w + bb.w, 0.f);
    *(float4*)(g_h + (size_t)warp * 128 + lane * 4) = o;
}

// ============ GEMM 2 (wmma): pq = h @ [Wl2|Wr2]  (N x 80) ============
// 256 threads (8 warps). Warp w: rows w*16..+15, all 80 cols (5 n-frags).

__global__ __launch_bounds__(256) void k_gemm2(void) {
    extern __shared__ __nv_bfloat16 sm[];
    __nv_bfloat16* AH  = sm;
    __nv_bfloat16* AL  = sm + 128 * TS;
    __nv_bfloat16* W2H = sm + 2 * 128 * TS;
    __nv_bfloat16* W2L = sm + 2 * 128 * TS + 128 * T2S;

    int tid = threadIdx.x;
    int wid = tid >> 5;
    int node0 = blockIdx.x * 128;

    // copy W2 splits (128x80) into padded smem
    {
        const uint4* sh = (const uint4*)g_w2h;
        const uint4* sl = (const uint4*)g_w2l;
        for (int g = tid; g < 1280; g += 256) {   // 128 rows x 10 uint4
            int row = g / 10, c = g % 10;
            *(uint4*)(W2H + row * T2S + c * 8) = sh[row * 10 + c];
            *(uint4*)(W2L + row * T2S + c * 8) = sl[row * 10 + c];
        }
    }
    conv_tile<256>(g_h, node0, AH, AL, tid);
    __syncthreads();

    wmma::fragment<wmma::accumulator, 16, 16, 16, float> C[5];
#pragma unroll
    for (int j = 0; j < 5; j++) wmma::fill_fragment(C[j], 0.0f);

#pragma unroll
    for (int k0 = 0; k0 < 8; k0++) {
        wmma::fragment<wmma::matrix_a, 16, 16, 16, __nv_bfloat16, wmma::row_major> ah, al;
        wmma::load_matrix_sync(ah, AH + (wid * 16) * TS + k0 * 16, TS);
        wmma::load_matrix_sync(al, AL + (wid * 16) * TS + k0 * 16, TS);
#pragma unroll
        for (int j = 0; j < 5; j++) {
            wmma::fragment<wmma::matrix_b, 16, 16, 16, __nv_bfloat16, wmma::row_major> bh, bl;
            wmma::load_matrix_sync(bh, W2H + (k0 * 16) * T2S + j * 16, T2S);
            wmma::load_matrix_sync(bl, W2L + (k0 * 16) * T2S + j * 16, T2S);
            wmma::mma_sync(C[j], ah, bh, C[j]);
            wmma::mma_sync(C[j], al, bh, C[j]);
            wmma::mma_sync(C[j], ah, bl, C[j]);
        }
    }

    float* dst = g_pq + (size_t)(node0 + wid * 16) * 80;
#pragma unroll
    for (int j = 0; j < 5; j++)
        wmma::store_matrix_sync(dst + j * 16, C[j], 80, wmma::mem_row_major);
}

// ---------- layer-2 aggregation + bias + log_softmax, fused (warp per node) ----------

__global__ void k_final(const float* __restrict__ b2, float* __restrict__ out) {
    int warp = (blockIdx.x * blockDim.x + threadIdx.x) >> 5;
    if (warp >= N_NODES) return;
    int lane = threadIdx.x & 31;
    int rs = g_rowstart[warp], re = g_rowstart[warp + 1];
    float acc0 = 0.f, acc1 = 0.f;
    for (int i0 = rs; i0 < re; i0 += 32) {
        int nv = min(32, re - i0);
        int s = (lane < nv) ? g_csrc[i0 + lane] : 0;
        for (int j = 0; j < nv; j++) {
            int sj = __shfl_sync(0xffffffffu, s, j);
            const float* pr = g_pq + (size_t)sj * 80;
            acc0 += pr[lane];
            if (lane < 8) acc1 += pr[32 + lane];
        }
    }
    float inv = 1.0f / fmaxf((float)(re - rs), 1.0f);
    const float* qr = g_pq + (size_t)warp * 80 + 40;
    float v0 = acc0 * inv + b2[lane] + qr[lane];
    float v1 = (lane < 8) ? (acc1 * inv + b2[32 + lane] + qr[32 + lane]) : -INFINITY;

    float mx = fmaxf(v0, v1);
#pragma unroll
    for (int o = 16; o; o >>= 1) mx = fmaxf(mx, __shfl_xor_sync(0xffffffffu, mx, o));
    float se = expf(v0 - mx) + ((lane < 8) ? expf(v1 - mx) : 0.f);
#pragma unroll
    for (int o = 16; o; o >>= 1) se += __shfl_xor_sync(0xffffffffu, se, o);
    float lse = logf(se);

    out[(size_t)warp * 40 + lane] = v0 - mx - lse;
    if (lane < 8) out[(size_t)warp * 40 + 32 + lane] = v1 - mx - lse;
}

// -------------------- launch --------------------

extern "C" void kernel_launch(void* const* d_in, const int* in_sizes, int n_in,
                              void* d_out, int out_size) {
    const float* x       = (const float*)d_in[0];
    const void*  ei      = d_in[1];
    const float* Wl1     = (const float*)d_in[2];
    const float* b1      = (const float*)d_in[3];
    const float* Wr1     = (const float*)d_in[4];
    const float* Wl2     = (const float*)d_in[5];
    const float* b2      = (const float*)d_in[6];
    const float* Wr2     = (const float*)d_in[7];
    float* out           = (float*)d_out;

    cudaFuncSetAttribute(k_gemm1, cudaFuncAttributeMaxDynamicSharedMemorySize, GEMM1_SMEM);
    cudaFuncSetAttribute(k_gemm2, cudaFuncAttributeMaxDynamicSharedMemorySize, GEMM2_SMEM);

    k_detect<<<1, 256>>>((const int*)ei);
    k_prep_w<<<1, 1024>>>(Wl1, Wr1, Wl2, Wr2);
    k_zero2<<<(N_NODES + 255) / 256, 256>>>();
    k_count<<<2048, 256>>>(ei);
    k_scan1<<<NB_SCAN, 1024>>>();
    k_scan2<<<1, 128>>>();
    k_scan3<<<NB_SCAN, 1024>>>();
    k_fill<<<2048, 256>>>(ei);
    k_gemm1<<<N_PAD / 128, 512, GEMM1_SMEM>>>(x);
    k_aggr_relu<<<(N_NODES * 32 + 255) / 256, 256>>>(b1);
    k_gemm2<<<N_PAD / 128, 256, GEMM2_SMEM>>>();
    k_final<<<(N_NODES * 32 + 255) / 256, 256>>>(b2, out);
}

// round 8
// speedup vs baseline: 1.7409x; 1.0893x over previous
#include <cuda_runtime.h>
#include <cuda_bf16.h>
#include <mma.h>
#include <math.h>
#include <cstdint>

using namespace nvcuda;

#define N_NODES 100000
#define N_EDGES 1600000
#define N_PAD 100096                          // 782*128
#define NB_SCAN ((N_NODES + 1023) / 1024)     // 98

#define TS 136                                // smem A/W tile stride (bf16 elems)
#define T2S 88                                // smem W2 tile stride
#define TILE_ELEMS (128 * TS)

// gemm1 smem: AH, AL, WLH, WLL, WRH, WRL  (6 x 128 x 136 bf16)
#define GEMM1_SMEM (6 * TILE_ELEMS * 2)
// gemm2 smem: AH, AL (128x136) + W2H, W2L (128x88)
#define GEMM2_SMEM ((2 * 128 * TS + 2 * 128 * T2S) * 2)

// -------- scratch (static __device__ globals; no runtime alloc) ----------
__device__ int   g_is64;
__device__ int   g_degi[N_NODES];
__device__ int   g_cursor[N_NODES];
__device__ int   g_rowstart[N_NODES + 1];
__device__ int   g_bsum[NB_SCAN];
__device__ int   g_boff[NB_SCAN];
__device__ int   g_csrc[N_EDGES];
__device__ float g_y1[(size_t)N_PAD * 128];   // x @ Wl1
__device__ float g_yr[(size_t)N_PAD * 128];   // x @ Wr1
__device__ float g_h[(size_t)N_NODES * 128];  // layer-1 output (relu)
__device__ float g_pq[(size_t)N_PAD * 80];    // [p(40) | q(40)] per node
// precomputed weight splits (bf16 hi/lo)
__device__ __nv_bfloat16 g_wl1h[16384], g_wl1l[16384];
__device__ __nv_bfloat16 g_wr1h[16384], g_wr1l[16384];
__device__ __nv_bfloat16 g_w2h[10240],  g_w2l[10240];   // [Wl2|Wr2] 128x80

// edge accessor: works for int32 or int64 edge_index
__device__ __forceinline__ int edge_at(const void* ei, long long idx) {
    if (g_is64) return (int)((const long long*)ei)[idx];
    return ((const int*)ei)[idx];
}

// -------------------- dtype detect + zero + weight prep --------------------
__global__ void k_detect(const int* __restrict__ ei32) {
    __shared__ int nz;
    if (threadIdx.x == 0) nz = 0;
    __syncthreads();
    if (ei32[2 * threadIdx.x + 1] != 0) atomicAdd(&nz, 1);
    __syncthreads();
    if (threadIdx.x == 0) g_is64 = (nz == 0) ? 1 : 0;
}

__global__ void k_zero2() {
    int i = blockIdx.x * blockDim.x + threadIdx.x;
    if (i < N_NODES) { g_degi[i] = 0; g_cursor[i] = 0; }
}

__device__ __forceinline__ void split1(float v, __nv_bfloat16& h, __nv_bfloat16& l) {
    h = __float2bfloat16_rn(v);
    l = __float2bfloat16_rn(v - __bfloat162float(h));
}

__global__ __launch_bounds__(1024) void k_prep_w(
    const float* __restrict__ Wl1, const float* __restrict__ Wr1,
    const float* __restrict__ Wl2, const float* __restrict__ Wr2) {
    for (int i = threadIdx.x; i < 16384; i += 1024) {
        split1(Wl1[i], g_wl1h[i], g_wl1l[i]);
        split1(Wr1[i], g_wr1h[i], g_wr1l[i]);
    }
    for (int i = threadIdx.x; i < 10240; i += 1024) {
        int k = i / 80, j = i % 80;
        float v = (j < 40) ? Wl2[k * 40 + j] : Wr2[k * 40 + (j - 40)];
        split1(v, g_w2h[i], g_w2l[i]);
    }
}

// -------------------- CSR build --------------------

__global__ void k_count(const void* __restrict__ ei) {
    for (int e = blockIdx.x * blockDim.x + threadIdx.x; e < N_EDGES;
         e += gridDim.x * blockDim.x) {
        int d = edge_at(ei, (long long)N_EDGES + e);
        atomicAdd(&g_degi[d], 1);
    }
}

__global__ __launch_bounds__(1024) void k_scan1() {
    __shared__ int wsum[32];
    int i = blockIdx.x * 1024 + threadIdx.x;
    int lane = threadIdx.x & 31, wid = threadIdx.x >> 5;
    int v = (i < N_NODES) ? g_degi[i] : 0;
    int pre = v;
#pragma unroll
    for (int o = 1; o < 32; o <<= 1) {
        int t = __shfl_up_sync(0xffffffffu, pre, o);
        if (lane >= o) pre += t;
    }
    if (lane == 31) wsum[wid] = pre;
    __syncthreads();
    if (wid == 0) {
        int w = wsum[lane];
        int p = w;
#pragma unroll
        for (int o = 1; o < 32; o <<= 1) {
            int t = __shfl_up_sync(0xffffffffu, p, o);
            if (lane >= o) p += t;
        }
        wsum[lane] = p - w;
        if (lane == 31) g_bsum[blockIdx.x] = p;
    }
    __syncthreads();
    if (i < N_NODES) g_rowstart[i] = pre - v + wsum[wid];
}

__global__ void k_scan2() {
    int t = threadIdx.x;            // 128 threads
    int lane = t & 31, wid = t >> 5;
    __shared__ int ws[4];
    int v = (t < NB_SCAN) ? g_bsum[t] : 0;
    int pre = v;
#pragma unroll
    for (int o = 1; o < 32; o <<= 1) {
        int u = __shfl_up_sync(0xffffffffu, pre, o);
        if (lane >= o) pre += u;
    }
    if (lane == 31) ws[wid] = pre;
    __syncthreads();
    if (t == 0) {
        int r = 0;
#pragma unroll
        for (int k = 0; k < 4; k++) { int tmp = ws[k]; ws[k] = r; r += tmp; }
        g_rowstart[N_NODES] = N_EDGES;
    }
    __syncthreads();
    if (t < NB_SCAN) g_boff[t] = pre - v + ws[wid];
}

__global__ __launch_bounds__(1024) void k_scan3() {
    int i = blockIdx.x * 1024 + threadIdx.x;
    if (i < N_NODES) g_rowstart[i] += g_boff[blockIdx.x];
}

__global__ void k_fill(const void* __restrict__ ei) {
    for (int e = blockIdx.x * blockDim.x + threadIdx.x; e < N_EDGES;
         e += gridDim.x * blockDim.x) {
        int d = edge_at(ei, (long long)N_EDGES + e);
        int s = edge_at(ei, e);
        int pos = atomicAdd(&g_cursor[d], 1);
        g_csrc[g_rowstart[d] + pos] = s;
    }
}

// ============ helpers for wmma GEMMs ============

// convert 4 fp32 -> hi/lo packed bf16x2 pairs
__device__ __forceinline__ void split4(float4 v, uint2& hi, uint2& lo) {
    __nv_bfloat162 h01 = __floats2bfloat162_rn(v.x, v.y);
    __nv_bfloat162 h23 = __floats2bfloat162_rn(v.z, v.w);
    float r0 = v.x - __low2float(h01),  r1 = v.y - __high2float(h01);
    float r2 = v.z - __low2float(h23),  r3 = v.w - __high2float(h23);
    __nv_bfloat162 l01 = __floats2bfloat162_rn(r0, r1);
    __nv_bfloat162 l23 = __floats2bfloat162_rn(r2, r3);
    hi = make_uint2(*(uint32_t*)&h01, *(uint32_t*)&h23);
    lo = make_uint2(*(uint32_t*)&l01, *(uint32_t*)&l23);
}

// convert 128x128 fp32 (row stride 128, rows clamped) into hi/lo smem tiles
template <int NTHREADS>
__device__ __forceinline__ void conv_tile(const float* __restrict__ src, int row0,
                                          __nv_bfloat16* H, __nv_bfloat16* L, int tid) {
    for (int g = tid; g < 4096; g += NTHREADS) {
        int row = g >> 5, c4 = g & 31;
        int r = row0 + row;
        if (r >= N_NODES) r = N_NODES - 1;
        float4 v = ((const float4*)(src + (size_t)r * 128))[c4];
        uint2 hi, lo;
        split4(v, hi, lo);
        *(uint2*)(H + row * TS + c4 * 4) = hi;
        *(uint2*)(L + row * TS + c4 * 4) = lo;
    }
}

// ============ GEMM 1: y1 = x@Wl1, yr = x@Wr1 (single A conversion) ============

__global__ __launch_bounds__(512) void k_gemm1(const float* __restrict__ x) {
    extern __shared__ __nv_bfloat16 sm[];
    __nv_bfloat16* AH  = sm;
    __nv_bfloat16* AL  = sm + TILE_ELEMS;
    __nv_bfloat16* WH0 = sm + 2 * TILE_ELEMS;  // WL hi
    __nv_bfloat16* WL0 = sm + 3 * TILE_ELEMS;  // WL lo
    __nv_bfloat16* WH1 = sm + 4 * TILE_ELEMS;  // WR hi
    __nv_bfloat16* WL1 = sm + 5 * TILE_ELEMS;  // WR lo

    int tid = threadIdx.x;
    int wid = tid >> 5;
    int node0 = blockIdx.x * 128;

    // copy precomputed weight splits into padded smem (one uint4 = 8 bf16)
    {
        const __nv_bfloat16* srcs[4] = {g_wl1h, g_wl1l, g_wr1h, g_wr1l};
        __nv_bfloat16* dsts[4] = {WH0, WL0, WH1, WL1};
#pragma unroll
        for (int tgt = 0; tgt < 4; tgt++) {
            const uint4* s = (const uint4*)srcs[tgt];
            for (int g = tid; g < 2048; g += 512) {   // 128 rows x 16 uint4
                int row = g >> 4, c = g & 15;
                *(uint4*)(dsts[tgt] + row * TS + c * 8) = s[row * 16 + c];
            }
        }
    }
    conv_tile<512>(x, node0, AH, AL, tid);
    __syncthreads();

    int out_sel = wid >> 3;          // 0: y1, 1: yr
    int w = wid & 7;
    int wm = w & 3;                  // rows wm*32
    int wn = w >> 2;                 // cols wn*64
    const __nv_bfloat16* WH = out_sel ? WH1 : WH0;
    const __nv_bfloat16* WL = out_sel ? WL1 : WL0;

    wmma::fragment<wmma::accumulator, 16, 16, 16, float> C[2][4];
#pragma unroll
    for (int i = 0; i < 2; i++)
#pragma unroll
        for (int j = 0; j < 4; j++) wmma::fill_fragment(C[i][j], 0.0f);

#pragma unroll
    for (int k0 = 0; k0 < 8; k0++) {
        wmma::fragment<wmma::matrix_a, 16, 16, 16, __nv_bfloat16, wmma::row_major> ah[2], al[2];
#pragma unroll
        for (int i = 0; i < 2; i++) {
            wmma::load_matrix_sync(ah[i], AH + (wm * 32 + i * 16) * TS + k0 * 16, TS);
            wmma::load_matrix_sync(al[i], AL + (wm * 32 + i * 16) * TS + k0 * 16, TS);
        }
#pragma unroll
        for (int j = 0; j < 4; j++) {
            wmma::fragment<wmma::matrix_b, 16, 16, 16, __nv_bfloat16, wmma::row_major> bh, bl;
            wmma::load_matrix_sync(bh, WH + (k0 * 16) * TS + wn * 64 + j * 16, TS);
            wmma::load_matrix_sync(bl, WL + (k0 * 16) * TS + wn * 64 + j * 16, TS);
#pragma unroll
            for (int i = 0; i < 2; i++) {
                wmma::mma_sync(C[i][j], ah[i], bh, C[i][j]);
                wmma::mma_sync(C[i][j], al[i], bh, C[i][j]);
                wmma::mma_sync(C[i][j], ah[i], bl, C[i][j]);
            }
        }
    }

    float* dst = (out_sel ? g_yr : g_y1) + (size_t)(node0 + wm * 32) * 128 + wn * 64;
#pragma unroll
    for (int i = 0; i < 2; i++)
#pragma unroll
        for (int j = 0; j < 4; j++)
            wmma::store_matrix_sync(dst + (size_t)i * 16 * 128 + j * 16, C[i][j],
                                    128, wmma::mem_row_major);
}

// ---------- h = relu(mean-gather(y1) + yr + b1)  (warp per node, MLP x4) ----------

__global__ void k_aggr_relu(const float* __restrict__ b1) {
    int warp = (blockIdx.x * blockDim.x + threadIdx.x) >> 5;
    if (warp >= N_NODES) return;
    int lane = threadIdx.x & 31;
    int rs = g_rowstart[warp], re = g_rowstart[warp + 1];
    float4 acc = make_float4(0.f, 0.f, 0.f, 0.f);
    for (int i0 = rs; i0 < re; i0 += 32) {
        int nv = min(32, re - i0);
        int s = (lane < nv) ? g_csrc[i0 + lane] : 0;
        int j = 0;
        for (; j + 4 <= nv; j += 4) {
            int s0 = __shfl_sync(0xffffffffu, s, j);
            int s1 = __shfl_sync(0xffffffffu, s, j + 1);
            int s2 = __shfl_sync(0xffffffffu, s, j + 2);
            int s3 = __shfl_sync(0xffffffffu, s, j + 3);
            float4 v0 = *(const float4*)(g_y1 + (size_t)s0 * 128 + lane * 4);
            float4 v1 = *(const float4*)(g_y1 + (size_t)s1 * 128 + lane * 4);
            float4 v2 = *(const float4*)(g_y1 + (size_t)s2 * 128 + lane * 4);
            float4 v3 = *(const float4*)(g_y1 + (size_t)s3 * 128 + lane * 4);
            acc.x += (v0.x + v1.x) + (v2.x + v3.x);
            acc.y += (v0.y + v1.y) + (v2.y + v3.y);
            acc.z += (v0.z + v1.z) + (v2.z + v3.z);
            acc.w += (v0.w + v1.w) + (v2.w + v3.w);
        }
        for (; j < nv; j++) {
            int sj = __shfl_sync(0xffffffffu, s, j);
            float4 v = *(const float4*)(g_y1 + (size_t)sj * 128 + lane * 4);
            acc.x += v.x; acc.y += v.y; acc.z += v.z; acc.w += v.w;
        }
    }
    float inv = 1.0f / fmaxf((float)(re - rs), 1.0f);
    float4 yr = *(const float4*)(g_yr + (size_t)warp * 128 + lane * 4);
    float4 bb = *(const float4*)(b1 + lane * 4);
    float4 o;
    o.x = fmaxf(acc.x * inv + yr.x + bb.x, 0.f);
    o.y = fmaxf(acc.y * inv + yr.y + bb.y, 0.f);
    o.z = fmaxf(acc.z * inv + yr.z + bb.z, 0.f);
    o.w = fmaxf(acc.w * inv + yr.w + bb.w, 0.f);
    *(float4*)(g_h + (size_t)warp * 128 + lane * 4) = o;
}

// ============ GEMM 2 (wmma): pq = h @ [Wl2|Wr2]  (N x 80) ============

__global__ __launch_bounds__(256) void k_gemm2(void) {
    extern __shared__ __nv_bfloat16 sm[];
    __nv_bfloat16* AH  = sm;
    __nv_bfloat16* AL  = sm + 128 * TS;
    __nv_bfloat16* W2H = sm + 2 * 128 * TS;
    __nv_bfloat16* W2L = sm + 2 * 128 * TS + 128 * T2S;

    int tid = threadIdx.x;
    int wid = tid >> 5;
    int node0 = blockIdx.x * 128;

    {
        const uint4* sh = (const uint4*)g_w2h;
        const uint4* sl = (const uint4*)g_w2l;
        for (int g = tid; g < 1280; g += 256) {   // 128 rows x 10 uint4
            int row = g / 10, c = g % 10;
            *(uint4*)(W2H + row * T2S + c * 8) = sh[row * 10 + c];
            *(uint4*)(W2L + row * T2S + c * 8) = sl[row * 10 + c];
        }
    }
    conv_tile<256>(g_h, node0, AH, AL, tid);
    __syncthreads();

    wmma::fragment<wmma::accumulator, 16, 16, 16, float> C[5];
#pragma unroll
    for (int j = 0; j < 5; j++) wmma::fill_fragment(C[j], 0.0f);

#pragma unroll
    for (int k0 = 0; k0 < 8; k0++) {
        wmma::fragment<wmma::matrix_a, 16, 16, 16, __nv_bfloat16, wmma::row_major> ah, al;
        wmma::load_matrix_sync(ah, AH + (wid * 16) * TS + k0 * 16, TS);
        wmma::load_matrix_sync(al, AL + (wid * 16) * TS + k0 * 16, TS);
#pragma unroll
        for (int j = 0; j < 5; j++) {
            wmma::fragment<wmma::matrix_b, 16, 16, 16, __nv_bfloat16, wmma::row_major> bh, bl;
            wmma::load_matrix_sync(bh, W2H + (k0 * 16) * T2S + j * 16, T2S);
            wmma::load_matrix_sync(bl, W2L + (k0 * 16) * T2S + j * 16, T2S);
            wmma::mma_sync(C[j], ah, bh, C[j]);
            wmma::mma_sync(C[j], al, bh, C[j]);
            wmma::mma_sync(C[j], ah, bl, C[j]);
        }
    }

    float* dst = g_pq + (size_t)(node0 + wid * 16) * 80;
#pragma unroll
    for (int j = 0; j < 5; j++)
        wmma::store_matrix_sync(dst + j * 16, C[j], 80, wmma::mem_row_major);
}

// ---------- layer-2 aggregation + bias + log_softmax (warp per node, MLP x4) ----------

__global__ void k_final(const float* __restrict__ b2, float* __restrict__ out) {
    int warp = (blockIdx.x * blockDim.x + threadIdx.x) >> 5;
    if (warp >= N_NODES) return;
    int lane = threadIdx.x & 31;
    int rs = g_rowstart[warp], re = g_rowstart[warp + 1];
    float acc0 = 0.f, acc1 = 0.f;
    for (int i0 = rs; i0 < re; i0 += 32) {
        int nv = min(32, re - i0);
        int s = (lane < nv) ? g_csrc[i0 + lane] : 0;
        int j = 0;
        for (; j + 4 <= nv; j += 4) {
            int s0 = __shfl_sync(0xffffffffu, s, j);
            int s1 = __shfl_sync(0xffffffffu, s, j + 1);
            int s2 = __shfl_sync(0xffffffffu, s, j + 2);
            int s3 = __shfl_sync(0xffffffffu, s, j + 3);
            const float* p0 = g_pq + (size_t)s0 * 80;
            const float* p1 = g_pq + (size_t)s1 * 80;
            const float* p2 = g_pq + (size_t)s2 * 80;
            const float* p3 = g_pq + (size_t)s3 * 80;
            float a0 = p0[lane], a1 = p1[lane], a2 = p2[lane], a3 = p3[lane];
            acc0 += (a0 + a1) + (a2 + a3);
            if (lane < 8) {
                float c0 = p0[32 + lane], c1 = p1[32 + lane];
                float c2 = p2[32 + lane], c3 = p3[32 + lane];
                acc1 += (c0 + c1) + (c2 + c3);
            }
        }
        for (; j < nv; j++) {
            int sj = __shfl_sync(0xffffffffu, s, j);
            const float* pr = g_pq + (size_t)sj * 80;
            acc0 += pr[lane];
            if (lane < 8) acc1 += pr[32 + lane];
        }
    }
    float inv = 1.0f / fmaxf((float)(re - rs), 1.0f);
    const float* qr = g_pq + (size_t)warp * 80 + 40;
    float v0 = acc0 * inv + b2[lane] + qr[lane];
    float v1 = (lane < 8) ? (acc1 * inv + b2[32 + lane] + qr[32 + lane]) : -INFINITY;

    float mx = fmaxf(v0, v1);
#pragma unroll
    for (int o = 16; o; o >>= 1) mx = fmaxf(mx, __shfl_xor_sync(0xffffffffu, mx, o));
    float se = expf(v0 - mx) + ((lane < 8) ? expf(v1 - mx) : 0.f);
#pragma unroll
    for (int o = 16; o; o >>= 1) se += __shfl_xor_sync(0xffffffffu, se, o);
    float lse = logf(se);

    out[(size_t)warp * 40 + lane] = v0 - mx - lse;
    if (lane < 8) out[(size_t)warp * 40 + 32 + lane] = v1 - mx - lse;
}

// -------------------- launch --------------------

extern "C" void kernel_launch(void* const* d_in, const int* in_sizes, int n_in,
                              void* d_out, int out_size) {
    const float* x       = (const float*)d_in[0];
    const void*  ei      = d_in[1];
    const float* Wl1     = (const float*)d_in[2];
    const float* b1      = (const float*)d_in[3];
    const float* Wr1     = (const float*)d_in[4];
    const float* Wl2     = (const float*)d_in[5];
    const float* b2      = (const float*)d_in[6];
    const float* Wr2     = (const float*)d_in[7];
    float* out           = (float*)d_out;

    cudaFuncSetAttribute(k_gemm1, cudaFuncAttributeMaxDynamicSharedMemorySize, GEMM1_SMEM);
    cudaFuncSetAttribute(k_gemm2, cudaFuncAttributeMaxDynamicSharedMemorySize, GEMM2_SMEM);

    // side stream + fork/join events (created once; handles cached — same work
    // happens on every call, so launches remain deterministic & capture-safe)
    static cudaStream_t s2 = nullptr;
    static cudaEvent_t ev_fork = nullptr, ev_join = nullptr;
    if (!s2) {
        cudaStreamCreateWithFlags(&s2, cudaStreamNonBlocking);
        cudaEventCreateWithFlags(&ev_fork, cudaEventDisableTiming);
        cudaEventCreateWithFlags(&ev_join, cudaEventDisableTiming);
    }

    k_detect<<<1, 256>>>((const int*)ei);
    k_prep_w<<<1, 1024>>>(Wl1, Wr1, Wl2, Wr2);

    // fork: gemm1 depends only on x + prep_w — run it alongside the CSR build
    cudaEventRecord(ev_fork, 0);
    cudaStreamWaitEvent(s2, ev_fork, 0);
    k_gemm1<<<N_PAD / 128, 512, GEMM1_SMEM, s2>>>(x);
    cudaEventRecord(ev_join, s2);

    // main stream: CSR build chain
    k_zero2<<<(N_NODES + 255) / 256, 256>>>();
    k_count<<<2048, 256>>>(ei);
    k_scan1<<<NB_SCAN, 1024>>>();
    k_scan2<<<1, 128>>>();
    k_scan3<<<NB_SCAN, 1024>>>();
    k_fill<<<2048, 256>>>(ei);

    // join: aggregation needs both CSR and y1/yr
    cudaStreamWaitEvent(0, ev_join, 0);
    k_aggr_relu<<<(N_NODES * 32 + 255) / 256, 256>>>(b1);
    k_gemm2<<<N_PAD / 128, 256, GEMM2_SMEM>>>();
    k_final<<<(N_NODES * 32 + 255) / 256, 256>>>(b2, out);
}

// round 9
// speedup vs baseline: 1.8692x; 1.0737x over previous
#include <cuda_runtime.h>
#include <cuda_bf16.h>
#include <cuda_fp16.h>
#include <mma.h>
#include <math.h>
#include <cstdint>

using namespace nvcuda;

#define N_NODES 100000
#define N_EDGES 1600000
#define N_PAD 100096                          // 782*128
#define NB_SCAN ((N_NODES + 1023) / 1024)     // 98

#define TS 136                                // smem A/W tile stride (bf16 elems)
#define T2S 88                                // smem W2 tile stride
#define TILE_ELEMS (128 * TS)

// gemm1 smem: AH, AL, WLH, WLL, WRH, WRL  (6 x 128 x 136 bf16)
#define GEMM1_SMEM (6 * TILE_ELEMS * 2)
// fused aggr+gemm2 smem: AH, AL (128x136 bf16) + W2H, W2L (128x88 bf16)
#define FUSED_SMEM ((2 * 128 * TS + 2 * 128 * T2S) * 2)

// -------- scratch (static __device__ globals; no runtime alloc) ----------
__device__ int    g_is64;
__device__ int    g_degi[N_NODES];
__device__ int    g_cursor[N_NODES];
__device__ int    g_rowstart[N_NODES + 1];
__device__ int    g_bsum[NB_SCAN];
__device__ int    g_boff[NB_SCAN];
__device__ int    g_csrc[N_EDGES];
__device__ __half g_y1h[(size_t)N_PAD * 128]; // x @ Wl1  (fp16 — gathered 16x per node)
__device__ float  g_yr[(size_t)N_PAD * 128];  // x @ Wr1  (fp32 — read once per node)
__device__ float  g_pq[(size_t)N_PAD * 80];   // [p(40) | q(40)] per node
// precomputed weight splits (bf16 hi/lo)
__device__ __nv_bfloat16 g_wl1h[16384], g_wl1l[16384];
__device__ __nv_bfloat16 g_wr1h[16384], g_wr1l[16384];
__device__ __nv_bfloat16 g_w2h[10240],  g_w2l[10240];   // [Wl2|Wr2] 128x80

// edge accessor: works for int32 or int64 edge_index
__device__ __forceinline__ int edge_at(const void* ei, long long idx) {
    if (g_is64) return (int)((const long long*)ei)[idx];
    return ((const int*)ei)[idx];
}

// -------------------- dtype detect + zero + weight prep --------------------
__global__ void k_detect(const int* __restrict__ ei32) {
    __shared__ int nz;
    if (threadIdx.x == 0) nz = 0;
    __syncthreads();
    if (ei32[2 * threadIdx.x + 1] != 0) atomicAdd(&nz, 1);
    __syncthreads();
    if (threadIdx.x == 0) g_is64 = (nz == 0) ? 1 : 0;
}

__global__ void k_zero2() {
    int i = blockIdx.x * blockDim.x + threadIdx.x;
    if (i < N_NODES) { g_degi[i] = 0; g_cursor[i] = 0; }
}

__device__ __forceinline__ void split1(float v, __nv_bfloat16& h, __nv_bfloat16& l) {
    h = __float2bfloat16_rn(v);
    l = __float2bfloat16_rn(v - __bfloat162float(h));
}

__global__ __launch_bounds__(1024) void k_prep_w(
    const float* __restrict__ Wl1, const float* __restrict__ Wr1,
    const float* __restrict__ Wl2, const float* __restrict__ Wr2) {
    for (int i = threadIdx.x; i < 16384; i += 1024) {
        split1(Wl1[i], g_wl1h[i], g_wl1l[i]);
        split1(Wr1[i], g_wr1h[i], g_wr1l[i]);
    }
    for (int i = threadIdx.x; i < 10240; i += 1024) {
        int k = i / 80, j = i % 80;
        float v = (j < 40) ? Wl2[k * 40 + j] : Wr2[k * 40 + (j - 40)];
        split1(v, g_w2h[i], g_w2l[i]);
    }
}

// -------------------- CSR build --------------------

__global__ void k_count(const void* __restrict__ ei) {
    for (int e = blockIdx.x * blockDim.x + threadIdx.x; e < N_EDGES;
         e += gridDim.x * blockDim.x) {
        int d = edge_at(ei, (long long)N_EDGES + e);
        atomicAdd(&g_degi[d], 1);
    }
}

__global__ __launch_bounds__(1024) void k_scan1() {
    __shared__ int wsum[32];
    int i = blockIdx.x * 1024 + threadIdx.x;
    int lane = threadIdx.x & 31, wid = threadIdx.x >> 5;
    int v = (i < N_NODES) ? g_degi[i] : 0;
    int pre = v;
#pragma unroll
    for (int o = 1; o < 32; o <<= 1) {
        int t = __shfl_up_sync(0xffffffffu, pre, o);
        if (lane >= o) pre += t;
    }
    if (lane == 31) wsum[wid] = pre;
    __syncthreads();
    if (wid == 0) {
        int w = wsum[lane];
        int p = w;
#pragma unroll
        for (int o = 1; o < 32; o <<= 1) {
            int t = __shfl_up_sync(0xffffffffu, p, o);
            if (lane >= o) p += t;
        }
        wsum[lane] = p - w;
        if (lane == 31) g_bsum[blockIdx.x] = p;
    }
    __syncthreads();
    if (i < N_NODES) g_rowstart[i] = pre - v + wsum[wid];
}

__global__ void k_scan2() {
    int t = threadIdx.x;            // 128 threads
    int lane = t & 31, wid = t >> 5;
    __shared__ int ws[4];
    int v = (t < NB_SCAN) ? g_bsum[t] : 0;
    int pre = v;
#pragma unroll
    for (int o = 1; o < 32; o <<= 1) {
        int u = __shfl_up_sync(0xffffffffu, pre, o);
        if (lane >= o) pre += u;
    }
    if (lane == 31) ws[wid] = pre;
    __syncthreads();
    if (t == 0) {
        int r = 0;
#pragma unroll
        for (int k = 0; k < 4; k++) { int tmp = ws[k]; ws[k] = r; r += tmp; }
        g_rowstart[N_NODES] = N_EDGES;
    }
    __syncthreads();
    if (t < NB_SCAN) g_boff[t] = pre - v + ws[wid];
}

__global__ __launch_bounds__(1024) void k_scan3() {
    int i = blockIdx.x * 1024 + threadIdx.x;
    if (i < N_NODES) g_rowstart[i] += g_boff[blockIdx.x];
}

__global__ void k_fill(const void* __restrict__ ei) {
    for (int e = blockIdx.x * blockDim.x + threadIdx.x; e < N_EDGES;
         e += gridDim.x * blockDim.x) {
        int d = edge_at(ei, (long long)N_EDGES + e);
        int s = edge_at(ei, e);
        int pos = atomicAdd(&g_cursor[d], 1);
        g_csrc[g_rowstart[d] + pos] = s;
    }
}

// ============ helpers for wmma GEMMs ============

// convert 4 fp32 -> hi/lo packed bf16x2 pairs
__device__ __forceinline__ void split4(float4 v, uint2& hi, uint2& lo) {
    __nv_bfloat162 h01 = __floats2bfloat162_rn(v.x, v.y);
    __nv_bfloat162 h23 = __floats2bfloat162_rn(v.z, v.w);
    float r0 = v.x - __low2float(h01),  r1 = v.y - __high2float(h01);
    float r2 = v.z - __low2float(h23),  r3 = v.w - __high2float(h23);
    __nv_bfloat162 l01 = __floats2bfloat162_rn(r0, r1);
    __nv_bfloat162 l23 = __floats2bfloat162_rn(r2, r3);
    hi = make_uint2(*(uint32_t*)&h01, *(uint32_t*)&h23);
    lo = make_uint2(*(uint32_t*)&l01, *(uint32_t*)&l23);
}

// convert 128x128 fp32 (row stride 128, rows clamped) into hi/lo smem tiles
template <int NTHREADS>
__device__ __forceinline__ void conv_tile(const float* __restrict__ src, int row0,
                                          __nv_bfloat16* H, __nv_bfloat16* L, int tid) {
    for (int g = tid; g < 4096; g += NTHREADS) {
        int row = g >> 5, c4 = g & 31;
        int r = row0 + row;
        if (r >= N_NODES) r = N_NODES - 1;
        float4 v = ((const float4*)(src + (size_t)r * 128))[c4];
        uint2 hi, lo;
        split4(v, hi, lo);
        *(uint2*)(H + row * TS + c4 * 4) = hi;
        *(uint2*)(L + row * TS + c4 * 4) = lo;
    }
}

// ============ GEMM 1: y1 = x@Wl1 (fp16 out), yr = x@Wr1 (fp32 out) ============
// 512 threads. Warps 0-7 -> y1 (weights WL), warps 8-15 -> yr (weights WR).

__global__ __launch_bounds__(512) void k_gemm1(const float* __restrict__ x) {
    extern __shared__ __nv_bfloat16 sm[];
    __nv_bfloat16* AH  = sm;
    __nv_bfloat16* AL  = sm + TILE_ELEMS;
    __nv_bfloat16* WH0 = sm + 2 * TILE_ELEMS;  // WL hi
    __nv_bfloat16* WL0 = sm + 3 * TILE_ELEMS;  // WL lo
    __nv_bfloat16* WH1 = sm + 4 * TILE_ELEMS;  // WR hi
    __nv_bfloat16* WL1 = sm + 5 * TILE_ELEMS;  // WR lo

    int tid = threadIdx.x;
    int wid = tid >> 5, lane = tid & 31;
    int node0 = blockIdx.x * 128;

    // copy precomputed weight splits into padded smem (one uint4 = 8 bf16)
    {
        const __nv_bfloat16* srcs[4] = {g_wl1h, g_wl1l, g_wr1h, g_wr1l};
        __nv_bfloat16* dsts[4] = {WH0, WL0, WH1, WL1};
#pragma unroll
        for (int tgt = 0; tgt < 4; tgt++) {
            const uint4* s = (const uint4*)srcs[tgt];
            for (int g = tid; g < 2048; g += 512) {   // 128 rows x 16 uint4
                int row = g >> 4, c = g & 15;
                *(uint4*)(dsts[tgt] + row * TS + c * 8) = s[row * 16 + c];
            }
        }
    }
    conv_tile<512>(x, node0, AH, AL, tid);
    __syncthreads();

    int out_sel = wid >> 3;          // 0: y1, 1: yr
    int w = wid & 7;
    int wm = w & 3;                  // rows wm*32
    int wn = w >> 2;                 // cols wn*64
    const __nv_bfloat16* WH = out_sel ? WH1 : WH0;
    const __nv_bfloat16* WL = out_sel ? WL1 : WL0;

    wmma::fragment<wmma::accumulator, 16, 16, 16, float> C[2][4];
#pragma unroll
    for (int i = 0; i < 2; i++)
#pragma unroll
        for (int j = 0; j < 4; j++) wmma::fill_fragment(C[i][j], 0.0f);

#pragma unroll
    for (int k0 = 0; k0 < 8; k0++) {
        wmma::fragment<wmma::matrix_a, 16, 16, 16, __nv_bfloat16, wmma::row_major> ah[2], al[2];
#pragma unroll
        for (int i = 0; i < 2; i++) {
            wmma::load_matrix_sync(ah[i], AH + (wm * 32 + i * 16) * TS + k0 * 16, TS);
            wmma::load_matrix_sync(al[i], AL + (wm * 32 + i * 16) * TS + k0 * 16, TS);
        }
#pragma unroll
        for (int j = 0; j < 4; j++) {
            wmma::fragment<wmma::matrix_b, 16, 16, 16, __nv_bfloat16, wmma::row_major> bh, bl;
            wmma::load_matrix_sync(bh, WH + (k0 * 16) * TS + wn * 64 + j * 16, TS);
            wmma::load_matrix_sync(bl, WL + (k0 * 16) * TS + wn * 64 + j * 16, TS);
#pragma unroll
            for (int i = 0; i < 2; i++) {
                wmma::mma_sync(C[i][j], ah[i], bh, C[i][j]);
                wmma::mma_sync(C[i][j], al[i], bh, C[i][j]);
                wmma::mma_sync(C[i][j], ah[i], bl, C[i][j]);
            }
        }
    }

    if (out_sel == 1) {
        // yr stays fp32, direct fragment store
        float* dst = g_yr + (size_t)(node0 + wm * 32) * 128 + wn * 64;
#pragma unroll
        for (int i = 0; i < 2; i++)
#pragma unroll
            for (int j = 0; j < 4; j++)
                wmma::store_matrix_sync(dst + (size_t)i * 16 * 128 + j * 16, C[i][j],
                                        128, wmma::mem_row_major);
    }
    __syncthreads();   // all mma reads of weight smem done -> safe to reuse as staging
    if (out_sel == 0) {
        // stage fp32 frags in smem, convert to fp16, store coalesced
        float* eb = (float*)sm + (size_t)w * 2048;   // 32x64 fp32 per warp
#pragma unroll
        for (int i = 0; i < 2; i++)
#pragma unroll
            for (int j = 0; j < 4; j++)
                wmma::store_matrix_sync(eb + i * 16 * 64 + j * 16, C[i][j], 64,
                                        wmma::mem_row_major);
        __syncwarp();
        for (int e = lane; e < 1024; e += 32) {      // 1024 half2 units (32r x 32)
            int r = e >> 5, c2 = e & 31;
            float2 v = ((const float2*)eb)[e];
            __half2 hv = __floats2half2_rn(v.x, v.y);
            *(__half2*)(g_y1h + (size_t)(node0 + wm * 32 + r) * 128 + wn * 64 + c2 * 2) = hv;
        }
    }
}

// ====== FUSED: h = relu(mean-gather(y1) + yr + b1)  ->  pq = h @ [Wl2|Wr2] ======
// 512 threads per CTA, 128 nodes per CTA.
// Phase A: warp w gathers nodes w*8..w*8+7; writes h split hi/lo into smem tiles.
// Phase B: wmma gemm2 from smem; warps 0-7: rows w*16, cols 0-47; warps 8-15: cols 48-79.

__global__ __launch_bounds__(512) void k_aggr_gemm2(const float* __restrict__ b1) {
    extern __shared__ __nv_bfloat16 sm[];
    __nv_bfloat16* AH  = sm;
    __nv_bfloat16* AL  = sm + TILE_ELEMS;
    __nv_bfloat16* W2H = sm + 2 * TILE_ELEMS;
    __nv_bfloat16* W2L = sm + 2 * TILE_ELEMS + 128 * T2S;

    int tid = threadIdx.x;
    int wid = tid >> 5, lane = tid & 31;
    int node0 = blockIdx.x * 128;

    // copy W2 splits (128x80) into padded smem
    {
        const uint4* sh = (const uint4*)g_w2h;
        const uint4* sl = (const uint4*)g_w2l;
        for (int g = tid; g < 1280; g += 512) {   // 128 rows x 10 uint4
            int row = g / 10, c = g % 10;
            *(uint4*)(W2H + row * T2S + c * 8) = sh[row * 10 + c];
            *(uint4*)(W2L + row * T2S + c * 8) = sl[row * 10 + c];
        }
    }

    // ---- Phase A: gather (y1 fp16) + relu, split into smem ----
    float4 bb = *(const float4*)(b1 + lane * 4);
#pragma unroll
    for (int i = 0; i < 8; i++) {
        int nl = wid * 8 + i;
        int node = node0 + nl;
        float4 h4 = make_float4(0.f, 0.f, 0.f, 0.f);
        if (node < N_NODES) {
            int rs = g_rowstart[node], re = g_rowstart[node + 1];
            float4 acc = make_float4(0.f, 0.f, 0.f, 0.f);
            for (int i0 = rs; i0 < re; i0 += 32) {
                int nv = min(32, re - i0);
                int s = (lane < nv) ? g_csrc[i0 + lane] : 0;
                int j = 0;
                for (; j + 8 <= nv; j += 8) {
                    uint2 u[8];
#pragma unroll
                    for (int t = 0; t < 8; t++) {
                        int sj = __shfl_sync(0xffffffffu, s, j + t);
                        u[t] = *(const uint2*)(g_y1h + (size_t)sj * 128 + lane * 4);
                    }
#pragma unroll
                    for (int t = 0; t < 8; t++) {
                        float2 a = __half22float2(*(const __half2*)&u[t].x);
                        float2 b = __half22float2(*(const __half2*)&u[t].y);
                        acc.x += a.x; acc.y += a.y; acc.z += b.x; acc.w += b.y;
                    }
                }
                for (; j < nv; j++) {
                    int sj = __shfl_sync(0xffffffffu, s, j);
                    uint2 u = *(const uint2*)(g_y1h + (size_t)sj * 128 + lane * 4);
                    float2 a = __half22float2(*(const __half2*)&u.x);
                    float2 b = __half22float2(*(const __half2*)&u.y);
                    acc.x += a.x; acc.y += a.y; acc.z += b.x; acc.w += b.y;
                }
            }
            float inv = 1.0f / fmaxf((float)(re - rs), 1.0f);
            float4 yr = *(const float4*)(g_yr + (size_t)node * 128 + lane * 4);
            h4.x = fmaxf(acc.x * inv + yr.x + bb.x, 0.f);
            h4.y = fmaxf(acc.y * inv + yr.y + bb.y, 0.f);
            h4.z = fmaxf(acc.z * inv + yr.z + bb.z, 0.f);
            h4.w = fmaxf(acc.w * inv + yr.w + bb.w, 0.f);
        }
        uint2 hi, lo;
        split4(h4, hi, lo);
        *(uint2*)(AH + nl * TS + lane * 4) = hi;
        *(uint2*)(AL + nl * TS + lane * 4) = lo;
    }
    __syncthreads();

    // ---- Phase B: wmma gemm2 ----
    int rblk = wid & 7;                 // rows rblk*16 .. +15
    int j0   = (wid < 8) ? 0 : 3;       // col frags {0,1,2} or {3,4}
    int nj   = (wid < 8) ? 3 : 2;

    wmma::fragment<wmma::accumulator, 16, 16, 16, float> C[3];
#pragma unroll
    for (int j = 0; j < 3; j++) wmma::fill_fragment(C[j], 0.0f);

#pragma unroll
    for (int k0 = 0; k0 < 8; k0++) {
        wmma::fragment<wmma::matrix_a, 16, 16, 16, __nv_bfloat16, wmma::row_major> ah, al;
        wmma::load_matrix_sync(ah, AH + (rblk * 16) * TS + k0 * 16, TS);
        wmma::load_matrix_sync(al, AL + (rblk * 16) * TS + k0 * 16, TS);
        for (int j = 0; j < nj; j++) {
            wmma::fragment<wmma::matrix_b, 16, 16, 16, __nv_bfloat16, wmma::row_major> bh, bl;
            wmma::load_matrix_sync(bh, W2H + (k0 * 16) * T2S + (j0 + j) * 16, T2S);
            wmma::load_matrix_sync(bl, W2L + (k0 * 16) * T2S + (j0 + j) * 16, T2S);
            wmma::mma_sync(C[j], ah, bh, C[j]);
            wmma::mma_sync(C[j], al, bh, C[j]);
            wmma::mma_sync(C[j], ah, bl, C[j]);
        }
    }

    float* dst = g_pq + (size_t)(node0 + rblk * 16) * 80;
    for (int j = 0; j < nj; j++)
        wmma::store_matrix_sync(dst + (j0 + j) * 16, C[j], 80, wmma::mem_row_major);
}

// ---------- layer-2 aggregation + bias + log_softmax (warp per node, MLP x4) ----------

__global__ void k_final(const float* __restrict__ b2, float* __restrict__ out) {
    int warp = (blockIdx.x * blockDim.x + threadIdx.x) >> 5;
    if (warp >= N_NODES) return;
    int lane = threadIdx.x & 31;
    int rs = g_rowstart[warp], re = g_rowstart[warp + 1];
    float acc0 = 0.f, acc1 = 0.f;
    for (int i0 = rs; i0 < re; i0 += 32) {
        int nv = min(32, re - i0);
        int s = (lane < nv) ? g_csrc[i0 + lane] : 0;
        int j = 0;
        for (; j + 4 <= nv; j += 4) {
            int s0 = __shfl_sync(0xffffffffu, s, j);
            int s1 = __shfl_sync(0xffffffffu, s, j + 1);
            int s2 = __shfl_sync(0xffffffffu, s, j + 2);
            int s3 = __shfl_sync(0xffffffffu, s, j + 3);
            const float* p0 = g_pq + (size_t)s0 * 80;
            const float* p1 = g_pq + (size_t)s1 * 80;
            const float* p2 = g_pq + (size_t)s2 * 80;
            const float* p3 = g_pq + (size_t)s3 * 80;
            float a0 = p0[lane], a1 = p1[lane], a2 = p2[lane], a3 = p3[lane];
            acc0 += (a0 + a1) + (a2 + a3);
            if (lane < 8) {
                float c0 = p0[32 + lane], c1 = p1[32 + lane];
                float c2 = p2[32 + lane], c3 = p3[32 + lane];
                acc1 += (c0 + c1) + (c2 + c3);
            }
        }
        for (; j < nv; j++) {
            int sj = __shfl_sync(0xffffffffu, s, j);
            const float* pr = g_pq + (size_t)sj * 80;
            acc0 += pr[lane];
            if (lane < 8) acc1 += pr[32 + lane];
        }
    }
    float inv = 1.0f / fmaxf((float)(re - rs), 1.0f);
    const float* qr = g_pq + (size_t)warp * 80 + 40;
    float v0 = acc0 * inv + b2[lane] + qr[lane];
    float v1 = (lane < 8) ? (acc1 * inv + b2[32 + lane] + qr[32 + lane]) : -INFINITY;

    float mx = fmaxf(v0, v1);
#pragma unroll
    for (int o = 16; o; o >>= 1) mx = fmaxf(mx, __shfl_xor_sync(0xffffffffu, mx, o));
    float se = expf(v0 - mx) + ((lane < 8) ? expf(v1 - mx) : 0.f);
#pragma unroll
    for (int o = 16; o; o >>= 1) se += __shfl_xor_sync(0xffffffffu, se, o);
    float lse = logf(se);

    out[(size_t)warp * 40 + lane] = v0 - mx - lse;
    if (lane < 8) out[(size_t)warp * 40 + 32 + lane] = v1 - mx - lse;
}

// -------------------- launch --------------------

extern "C" void kernel_launch(void* const* d_in, const int* in_sizes, int n_in,
                              void* d_out, int out_size) {
    const float* x       = (const float*)d_in[0];
    const void*  ei      = d_in[1];
    const float* Wl1     = (const float*)d_in[2];
    const float* b1      = (const float*)d_in[3];
    const float* Wr1     = (const float*)d_in[4];
    const float* Wl2     = (const float*)d_in[5];
    const float* b2      = (const float*)d_in[6];
    const float* Wr2     = (const float*)d_in[7];
    float* out           = (float*)d_out;

    cudaFuncSetAttribute(k_gemm1, cudaFuncAttributeMaxDynamicSharedMemorySize, GEMM1_SMEM);
    cudaFuncSetAttribute(k_aggr_gemm2, cudaFuncAttributeMaxDynamicSharedMemorySize, FUSED_SMEM);

    // side stream + fork/join events (created once; deterministic work per call)
    static cudaStream_t s2 = nullptr;
    static cudaEvent_t ev_fork = nullptr, ev_join = nullptr;
    if (!s2) {
        cudaStreamCreateWithFlags(&s2, cudaStreamNonBlocking);
        cudaEventCreateWithFlags(&ev_fork, cudaEventDisableTiming);
        cudaEventCreateWithFlags(&ev_join, cudaEventDisableTiming);
    }

    k_detect<<<1, 256>>>((const int*)ei);
    k_prep_w<<<1, 1024>>>(Wl1, Wr1, Wl2, Wr2);

    // fork: gemm1 depends only on x + prep_w — run it alongside the CSR build
    cudaEventRecord(ev_fork, 0);
    cudaStreamWaitEvent(s2, ev_fork, 0);
    k_gemm1<<<N_PAD / 128, 512, GEMM1_SMEM, s2>>>(x);
    cudaEventRecord(ev_join, s2);

    // main stream: CSR build chain
    k_zero2<<<(N_NODES + 255) / 256, 256>>>();
    k_count<<<2048, 256>>>(ei);
    k_scan1<<<NB_SCAN, 1024>>>();
    k_scan2<<<1, 128>>>();
    k_scan3<<<NB_SCAN, 1024>>>();
    k_fill<<<2048, 256>>>(ei);

    // join: fused aggregation+gemm2 needs both CSR and y1/yr
    cudaStreamWaitEvent(0, ev_join, 0);
    k_aggr_gemm2<<<N_PAD / 128, 512, FUSED_SMEM>>>(b1);
    k_final<<<(N_NODES * 32 + 255) / 256, 256>>>(b2, out);
}